// round 1
// baseline (speedup 1.0000x reference)
#include <cuda_runtime.h>
#include <math.h>

// Problem constants
constexpr int Bz  = 4;
constexpr int Pz  = 2048;
constexpr int Dz  = 1024;   // model dim; also H*DK
constexpr int Hz  = 16;
constexpr int DKz = 64;
constexpr int Mrows = Bz * Pz;          // 8192
constexpr int HD   = Hz * DKz;          // 1024

// ---------------- scratch (allocation-free rule: __device__ globals) -------
__device__ float g_Q[(size_t)Mrows * HD];
__device__ float g_K[(size_t)Mrows * HD];
__device__ float g_V[(size_t)Mrows * HD];
__device__ float g_REP[(size_t)Mrows * HD];

// =====================================================================
// SGEMM with bias: C[M,N] = A[M,K] @ W[K,N] + bias[N]
// BM=BN=128, BK=8, 256 threads, 8x8 per-thread microtile
// =====================================================================
constexpr int BM = 128, BN = 128, BK = 8;

__global__ __launch_bounds__(256, 2)
void sgemm_bias(const float* __restrict__ A, const float* __restrict__ W,
                const float* __restrict__ bias, float* __restrict__ C,
                int M, int N, int K)
{
    __shared__ float As[BK][BM];   // transposed A tile
    __shared__ float Bs[BK][BN];

    const int tid = threadIdx.x;
    const int tc  = tid & 15;      // 0..15 (col group)
    const int tr  = tid >> 4;      // 0..15 (row group)
    const int bm  = blockIdx.y;
    const int bn  = blockIdx.x;

    const float* Ab = A + (size_t)bm * BM * K;
    const float* Wb = W + (size_t)bn * BN;

    // gmem load mapping
    const int arow = tid >> 1;            // 0..127
    const int acol = (tid & 1) * 4;       // 0 or 4
    const int brow = tid >> 5;            // 0..7
    const int bcol = (tid & 31) * 4;      // 0..124

    float acc[8][8];
#pragma unroll
    for (int i = 0; i < 8; i++)
#pragma unroll
        for (int j = 0; j < 8; j++) acc[i][j] = 0.f;

    for (int kt = 0; kt < K; kt += BK) {
        float4 av = *reinterpret_cast<const float4*>(Ab + (size_t)arow * K + kt + acol);
        float4 bv = *reinterpret_cast<const float4*>(Wb + (size_t)(kt + brow) * N + bcol);

        __syncthreads();   // previous compute done before overwriting tiles
        As[acol + 0][arow] = av.x;
        As[acol + 1][arow] = av.y;
        As[acol + 2][arow] = av.z;
        As[acol + 3][arow] = av.w;
        *reinterpret_cast<float4*>(&Bs[brow][bcol]) = bv;
        __syncthreads();

#pragma unroll
        for (int k = 0; k < BK; k++) {
            float4 a0 = *reinterpret_cast<const float4*>(&As[k][tr * 8]);
            float4 a1 = *reinterpret_cast<const float4*>(&As[k][tr * 8 + 4]);
            float4 b0 = *reinterpret_cast<const float4*>(&Bs[k][tc * 8]);
            float4 b1 = *reinterpret_cast<const float4*>(&Bs[k][tc * 8 + 4]);
            float a[8] = {a0.x, a0.y, a0.z, a0.w, a1.x, a1.y, a1.z, a1.w};
            float b[8] = {b0.x, b0.y, b0.z, b0.w, b1.x, b1.y, b1.z, b1.w};
#pragma unroll
            for (int i = 0; i < 8; i++)
#pragma unroll
                for (int j = 0; j < 8; j++)
                    acc[i][j] = fmaf(a[i], b[j], acc[i][j]);
        }
    }

    // epilogue with bias
    const int ccol0 = bn * BN + tc * 8;
    float bb[8];
#pragma unroll
    for (int j = 0; j < 8; j++) bb[j] = bias[ccol0 + j];

#pragma unroll
    for (int i = 0; i < 8; i++) {
        const int crow = bm * BM + tr * 8 + i;
        float4 r0, r1;
        r0.x = acc[i][0] + bb[0]; r0.y = acc[i][1] + bb[1];
        r0.z = acc[i][2] + bb[2]; r0.w = acc[i][3] + bb[3];
        r1.x = acc[i][4] + bb[4]; r1.y = acc[i][5] + bb[5];
        r1.z = acc[i][6] + bb[6]; r1.w = acc[i][7] + bb[7];
        *reinterpret_cast<float4*>(C + (size_t)crow * N + ccol0)     = r0;
        *reinterpret_cast<float4*>(C + (size_t)crow * N + ccol0 + 4) = r1;
    }
}

// =====================================================================
// Flash attention: for each (b,h), O = softmax(Q K^T / 8) V
// BR=BC=DK=64, 256 threads, 4x4 fragments in both GEMM phases
// =====================================================================
constexpr int BR = 64, BC = 64, PAD = 68;
constexpr int FLASH_SMEM = (5 * 64 * PAD + 3 * 64) * 4;   // 87808 bytes

__global__ __launch_bounds__(256, 2)
void flash_kernel(const float* __restrict__ Qg, const float* __restrict__ Kg,
                  const float* __restrict__ Vg, float* __restrict__ Og)
{
    extern __shared__ float sm[];
    float* QsT = sm;                       // [DK][PAD] : [d][r]
    float* KsT = QsT + 64 * PAD;           // [d][j]
    float* Vs  = KsT + 64 * PAD;           // [j][d]
    float* Ss  = Vs  + 64 * PAD;           // [r][c]   scores
    float* PT  = Ss  + 64 * PAD;           // [j][r]   probs (transposed)
    float* rowm = PT + 64 * PAD;           // [64]
    float* rowl = rowm + 64;               // [64]
    float* rowscale = rowl + 64;           // [64]

    const int tid = threadIdx.x;
    const int tx  = tid & 15;
    const int ty  = tid >> 4;
    const int qt  = blockIdx.x;
    const int h   = blockIdx.y;
    const int b   = blockIdx.z;
    const float scale = 0.125f;            // 1/sqrt(64)

    const size_t base = (size_t)b * Pz * HD + (size_t)h * DKz;
    const float* Qp = Qg + base + (size_t)qt * BR * HD;

    // load Q tile -> QsT[d][r]
#pragma unroll
    for (int it = 0; it < 4; it++) {
        int lin = tid + it * 256;
        int r  = lin >> 4;
        int d0 = (lin & 15) * 4;
        float4 v = *reinterpret_cast<const float4*>(Qp + (size_t)r * HD + d0);
        QsT[(d0 + 0) * PAD + r] = v.x;
        QsT[(d0 + 1) * PAD + r] = v.y;
        QsT[(d0 + 2) * PAD + r] = v.z;
        QsT[(d0 + 3) * PAD + r] = v.w;
    }
    if (tid < 64) { rowm[tid] = -1e30f; rowl[tid] = 0.f; }

    float o[4][4];
#pragma unroll
    for (int i = 0; i < 4; i++)
#pragma unroll
        for (int j = 0; j < 4; j++) o[i][j] = 0.f;

    const int nTiles = Pz / BC;            // 32
    for (int t = 0; t < nTiles; t++) {
        const float* Kp = Kg + base + (size_t)t * BC * HD;
        const float* Vp = Vg + base + (size_t)t * BC * HD;

        __syncthreads();   // prev iter readers done (also covers Q load / init)
#pragma unroll
        for (int it = 0; it < 4; it++) {
            int lin = tid + it * 256;
            int j  = lin >> 4;
            int d0 = (lin & 15) * 4;
            float4 kv = *reinterpret_cast<const float4*>(Kp + (size_t)j * HD + d0);
            KsT[(d0 + 0) * PAD + j] = kv.x;
            KsT[(d0 + 1) * PAD + j] = kv.y;
            KsT[(d0 + 2) * PAD + j] = kv.z;
            KsT[(d0 + 3) * PAD + j] = kv.w;
            float4 vv = *reinterpret_cast<const float4*>(Vp + (size_t)j * HD + d0);
            *reinterpret_cast<float4*>(Vs + j * PAD + d0) = vv;
        }
        __syncthreads();

        // ---- Phase A: S = Q K^T (4x4 fragment per thread) ----
        float s[4][4];
#pragma unroll
        for (int i = 0; i < 4; i++)
#pragma unroll
            for (int j = 0; j < 4; j++) s[i][j] = 0.f;

#pragma unroll 8
        for (int d = 0; d < 64; d++) {
            float4 qv = *reinterpret_cast<const float4*>(QsT + d * PAD + ty * 4);
            float4 kv = *reinterpret_cast<const float4*>(KsT + d * PAD + tx * 4);
            float qa[4] = {qv.x, qv.y, qv.z, qv.w};
            float ka[4] = {kv.x, kv.y, kv.z, kv.w};
#pragma unroll
            for (int i = 0; i < 4; i++)
#pragma unroll
                for (int j = 0; j < 4; j++)
                    s[i][j] = fmaf(qa[i], ka[j], s[i][j]);
        }
#pragma unroll
        for (int i = 0; i < 4; i++)
#pragma unroll
            for (int j = 0; j < 4; j++)
                Ss[(ty * 4 + i) * PAD + tx * 4 + j] = s[i][j] * scale;
        __syncthreads();

        // ---- Phase B: online softmax (4 threads per row) ----
        {
            const int row = tid >> 2;
            const int cg  = tid & 3;
            float sv[16];
            float mloc = -1e30f;
#pragma unroll
            for (int jj = 0; jj < 16; jj++) {
                sv[jj] = Ss[row * PAD + cg * 16 + jj];
                mloc = fmaxf(mloc, sv[jj]);
            }
            mloc = fmaxf(mloc, __shfl_xor_sync(0xffffffffu, mloc, 1));
            mloc = fmaxf(mloc, __shfl_xor_sync(0xffffffffu, mloc, 2));
            const float mold = rowm[row];
            const float mnew = fmaxf(mold, mloc);
            float lsum = 0.f;
#pragma unroll
            for (int jj = 0; jj < 16; jj++) {
                float p = __expf(sv[jj] - mnew);
                lsum += p;
                PT[(cg * 16 + jj) * PAD + row] = p;
            }
            lsum += __shfl_xor_sync(0xffffffffu, lsum, 1);
            lsum += __shfl_xor_sync(0xffffffffu, lsum, 2);
            if (cg == 0) {
                float sc = __expf(mold - mnew);
                rowscale[row] = sc;
                rowm[row] = mnew;
                rowl[row] = rowl[row] * sc + lsum;
            }
        }
        __syncthreads();

        // ---- Phase C: O = O*scale + P V ----
        float sc4[4];
#pragma unroll
        for (int i = 0; i < 4; i++) sc4[i] = rowscale[ty * 4 + i];
#pragma unroll
        for (int i = 0; i < 4; i++)
#pragma unroll
            for (int j = 0; j < 4; j++) o[i][j] *= sc4[i];

#pragma unroll 8
        for (int jk = 0; jk < 64; jk++) {
            float4 pv = *reinterpret_cast<const float4*>(PT + jk * PAD + ty * 4);
            float4 vv = *reinterpret_cast<const float4*>(Vs + jk * PAD + tx * 4);
            float pa[4] = {pv.x, pv.y, pv.z, pv.w};
            float va[4] = {vv.x, vv.y, vv.z, vv.w};
#pragma unroll
            for (int i = 0; i < 4; i++)
#pragma unroll
                for (int j = 0; j < 4; j++)
                    o[i][j] = fmaf(pa[i], va[j], o[i][j]);
        }
    }

    // finalize: divide by l and store
    float invl[4];
#pragma unroll
    for (int i = 0; i < 4; i++) invl[i] = 1.f / rowl[ty * 4 + i];

    float* Op = Og + base + (size_t)qt * BR * HD;
#pragma unroll
    for (int i = 0; i < 4; i++) {
        float4 w;
        w.x = o[i][0] * invl[i];
        w.y = o[i][1] * invl[i];
        w.z = o[i][2] * invl[i];
        w.w = o[i][3] * invl[i];
        *reinterpret_cast<float4*>(Op + (size_t)(ty * 4 + i) * HD + tx * 4) = w;
    }
}

// =====================================================================
// launcher
// =====================================================================
extern "C" void kernel_launch(void* const* d_in, const int* in_sizes, int n_in,
                              void* d_out, int out_size)
{
    const float* x  = (const float*)d_in[0];
    const float* Wq = (const float*)d_in[1];
    const float* bq = (const float*)d_in[2];
    const float* Wk = (const float*)d_in[3];
    const float* bk = (const float*)d_in[4];
    const float* Wv = (const float*)d_in[5];
    const float* bv = (const float*)d_in[6];
    const float* Wo = (const float*)d_in[7];
    const float* bo = (const float*)d_in[8];

    float *q, *k, *v, *rep;
    cudaGetSymbolAddress((void**)&q,   g_Q);
    cudaGetSymbolAddress((void**)&k,   g_K);
    cudaGetSymbolAddress((void**)&v,   g_V);
    cudaGetSymbolAddress((void**)&rep, g_REP);

    cudaFuncSetAttribute(flash_kernel,
                         cudaFuncAttributeMaxDynamicSharedMemorySize, FLASH_SMEM);

    dim3 gg(Dz / BN, Mrows / BM);   // (8, 64)

    sgemm_bias<<<gg, 256>>>(x, Wq, bq, q, Mrows, HD, Dz);
    sgemm_bias<<<gg, 256>>>(x, Wk, bk, k, Mrows, HD, Dz);
    sgemm_bias<<<gg, 256>>>(x, Wv, bv, v, Mrows, HD, Dz);

    flash_kernel<<<dim3(Pz / BR, Hz, Bz), 256, FLASH_SMEM>>>(q, k, v, rep);

    sgemm_bias<<<gg, 256>>>(rep, Wo, bo, (float*)d_out, Mrows, Dz, HD);
}

// round 4
// speedup vs baseline: 1.4557x; 1.4557x over previous
#include <cuda_runtime.h>
#include <cuda_bf16.h>
#include <cstdint>
#include <math.h>

// Problem constants
constexpr int Bz  = 4;
constexpr int Pz  = 2048;
constexpr int Dz  = 1024;   // model dim; N and K of every GEMM
constexpr int Hz  = 16;
constexpr int DKz = 64;
constexpr int Mrows = Bz * Pz;          // 8192
constexpr int HD   = Hz * DKz;          // 1024

// ---------------- scratch (allocation-free rule: __device__ globals) -------
__device__ float g_Q  [(size_t)Mrows * HD];
__device__ float g_K  [(size_t)Mrows * HD];
__device__ float g_V  [(size_t)Mrows * HD];
__device__ float g_REP[(size_t)Mrows * HD];
__device__ __nv_bfloat16 g_xh [(size_t)Mrows * Dz];   // activation hi
__device__ __nv_bfloat16 g_xl [(size_t)Mrows * Dz];   // activation lo
__device__ __nv_bfloat16 g_wht[(size_t)Dz * Dz];      // W^T hi  [N,K]
__device__ __nv_bfloat16 g_wlt[(size_t)Dz * Dz];      // W^T lo  [N,K]

// =====================================================================
// baseline-PTX helpers (work on .target sm_103: no 'a' features!)
// =====================================================================
__device__ __forceinline__ uint32_t smem_u32(const void* p) {
    uint32_t a;
    asm("{ .reg .u64 t; cvta.to.shared.u64 t, %1; cvt.u32.u64 %0, t; }"
        : "=r"(a) : "l"(p));
    return a;
}
#define LDSM_X4(r0, r1, r2, r3, addr) \
    asm volatile("ldmatrix.sync.aligned.m8n8.x4.shared.b16 {%0,%1,%2,%3}, [%4];" \
                 : "=r"(r0), "=r"(r1), "=r"(r2), "=r"(r3) : "r"(addr))
#define CP_ASYNC16(dst, src) \
    asm volatile("cp.async.ca.shared.global [%0], [%1], 16;" :: "r"(dst), "l"(src))
#define CP_COMMIT() asm volatile("cp.async.commit_group;" ::: "memory")
#define CP_WAIT1()  asm volatile("cp.async.wait_group 1;" ::: "memory")
#define CP_WAIT0()  asm volatile("cp.async.wait_group 0;" ::: "memory")

__device__ __forceinline__ void mma_bf16(float* c, const uint32_t a[4],
                                         uint32_t b0, uint32_t b1) {
    asm volatile(
        "mma.sync.aligned.m16n8k16.row.col.f32.bf16.bf16.f32 "
        "{%0,%1,%2,%3}, {%4,%5,%6,%7}, {%8,%9}, {%0,%1,%2,%3};"
        : "+f"(c[0]), "+f"(c[1]), "+f"(c[2]), "+f"(c[3])
        : "r"(a[0]), "r"(a[1]), "r"(a[2]), "r"(a[3]), "r"(b0), "r"(b1));
}

// =====================================================================
// split helpers
// =====================================================================
__device__ __forceinline__ void split2(float x, __nv_bfloat16& h, __nv_bfloat16& l) {
    h = __float2bfloat16_rn(x);
    l = __float2bfloat16_rn(x - __bfloat162float(h));
}

__global__ void split_kernel(const float4* __restrict__ src,
                             __nv_bfloat162* __restrict__ hi,
                             __nv_bfloat162* __restrict__ lo, int n4)
{
    int i = blockIdx.x * blockDim.x + threadIdx.x;
    int stride = gridDim.x * blockDim.x;
    for (; i < n4; i += stride) {
        float4 v = src[i];
        __nv_bfloat16 h0, h1, h2, h3, l0, l1, l2, l3;
        split2(v.x, h0, l0); split2(v.y, h1, l1);
        split2(v.z, h2, l2); split2(v.w, h3, l3);
        hi[2 * i]     = __halves2bfloat162(h0, h1);
        hi[2 * i + 1] = __halves2bfloat162(h2, h3);
        lo[2 * i]     = __halves2bfloat162(l0, l1);
        lo[2 * i + 1] = __halves2bfloat162(l2, l3);
    }
}

// transpose + split: W[K,N] fp32 -> WhT/WlT [N,K] bf16
__global__ void wsplit_kernel(const float* __restrict__ W,
                              __nv_bfloat16* __restrict__ WhT,
                              __nv_bfloat16* __restrict__ WlT)
{
    __shared__ float s[32][33];
    const int n0 = blockIdx.x * 32, k0 = blockIdx.y * 32;
    const int tx = threadIdx.x, ty = threadIdx.y;   // (32, 8)
#pragma unroll
    for (int i = 0; i < 4; i++)
        s[ty + i * 8][tx] = W[(size_t)(k0 + ty + i * 8) * Dz + n0 + tx];
    __syncthreads();
#pragma unroll
    for (int i = 0; i < 4; i++) {
        const int n = n0 + ty + i * 8;
        const int k = k0 + tx;
        float v = s[tx][ty + i * 8];
        __nv_bfloat16 h, l;
        split2(v, h, l);
        WhT[(size_t)n * Dz + k] = h;
        WlT[(size_t)n * Dz + k] = l;
    }
}

// =====================================================================
// HMMA split-bf16 GEMM: C[8192,1024] = A @ W + bias
// A as (Ah,Al) [M,K] bf16; W as (BhT,BlT) [N,K] bf16.
// CTA 128x128, BK=32, 8 warps (warp tile 64x32), cp.async double buffer.
// SMEM row stride 40 bf16 (80B) -> conflict-free ldmatrix.
// =====================================================================
constexpr int SKB   = 80;                  // smem row stride bytes
constexpr int TILEB = 128 * SKB;           // 10240 per tile
constexpr int BUFB  = 4 * TILEB;           // Ah,Al,Bh,Bl = 40960
constexpr int GEMM_SMEM = 2 * BUFB;        // 81920

__global__ __launch_bounds__(256)
void gemm_hmma3(const __nv_bfloat16* __restrict__ Ah, const __nv_bfloat16* __restrict__ Al,
                const __nv_bfloat16* __restrict__ Bh, const __nv_bfloat16* __restrict__ Bl,
                const float* __restrict__ bias, float* __restrict__ C)
{
    extern __shared__ char smem[];
    const uint32_t sbase = smem_u32(smem);
    const int tid  = threadIdx.x;
    const int lane = tid & 31;
    const int wid  = tid >> 5;
    const int wm   = wid >> 2;       // 0..1  (64 rows each)
    const int wn   = wid & 3;        // 0..3  (32 cols each)
    const int m0 = blockIdx.y * 128;
    const int n0 = blockIdx.x * 128;

    const __nv_bfloat16* srcs[4] = {
        Ah + (size_t)m0 * Dz, Al + (size_t)m0 * Dz,
        Bh + (size_t)n0 * Dz, Bl + (size_t)n0 * Dz };

    float acc[4][4][4];
#pragma unroll
    for (int mi = 0; mi < 4; mi++)
#pragma unroll
        for (int ni = 0; ni < 4; ni++)
#pragma unroll
            for (int r = 0; r < 4; r++) acc[mi][ni][r] = 0.f;

    // cp.async: per tile 128 rows x 64B = 512 x 16B; 2 per thread
    auto issue = [&](int t, int b) {
#pragma unroll
        for (int p = 0; p < 4; p++) {
            const __nv_bfloat16* s = srcs[p] + t * 32;
            const uint32_t dT = sbase + b * BUFB + p * TILEB;
#pragma unroll
            for (int i = 0; i < 2; i++) {
                int lin = tid + i * 256;           // 0..511
                int row = lin >> 2, kg = lin & 3;
                CP_ASYNC16(dT + row * SKB + kg * 16,
                           s + (size_t)row * Dz + kg * 8);
            }
        }
        CP_COMMIT();
    };

    // ldmatrix address components
    const uint32_t aRow = lane & 15;               // A: rows of the m16 tile
    const uint32_t aK   = (lane >> 4) * 8;         // k half
    const uint32_t bN   = ((lane >> 4) & 1) * 8 + (lane & 7);
    const uint32_t bK   = ((lane >> 3) & 1) * 8;

    issue(0, 0);
    const int nk = Dz / 32;                        // 32 chunks
    for (int t = 0; t < nk; t++) {
        if (t + 1 < nk) { issue(t + 1, (t + 1) & 1); CP_WAIT1(); }
        else            { CP_WAIT0(); }
        __syncthreads();

        const uint32_t bb  = sbase + (t & 1) * BUFB;
        const uint32_t ahB = bb, alB = bb + TILEB;
        const uint32_t bhB = bb + 2 * TILEB, blB = bb + 3 * TILEB;

#pragma unroll
        for (int ks = 0; ks < 32; ks += 16) {
            const uint32_t aoff = (aK + ks) * 2;
            const uint32_t boff = (bK + ks) * 2;

            uint32_t Ahf[4][4], Bhf[4][2];
            // B hi: 2 x ldmatrix.x4, each covers two n8 tiles
#pragma unroll
            for (int p = 0; p < 2; p++) {
                uint32_t r0, r1, r2, r3;
                LDSM_X4(r0, r1, r2, r3,
                        bhB + (wn * 32 + p * 16 + bN) * SKB + boff);
                Bhf[2 * p][0] = r0; Bhf[2 * p][1] = r1;
                Bhf[2 * p + 1][0] = r2; Bhf[2 * p + 1][1] = r3;
            }
            // A hi: 4 x ldmatrix.x4 (one per m16 tile)
#pragma unroll
            for (int mi = 0; mi < 4; mi++)
                LDSM_X4(Ahf[mi][0], Ahf[mi][1], Ahf[mi][2], Ahf[mi][3],
                        ahB + (wm * 64 + mi * 16 + aRow) * SKB + aoff);
            // term 1: Ah x Bh
#pragma unroll
            for (int mi = 0; mi < 4; mi++)
#pragma unroll
                for (int ni = 0; ni < 4; ni++)
                    mma_bf16(acc[mi][ni], Ahf[mi], Bhf[ni][0], Bhf[ni][1]);
            // term 2: Al x Bh
#pragma unroll
            for (int mi = 0; mi < 4; mi++) {
                uint32_t Alf[4];
                LDSM_X4(Alf[0], Alf[1], Alf[2], Alf[3],
                        alB + (wm * 64 + mi * 16 + aRow) * SKB + aoff);
#pragma unroll
                for (int ni = 0; ni < 4; ni++)
                    mma_bf16(acc[mi][ni], Alf, Bhf[ni][0], Bhf[ni][1]);
            }
            // term 3: Ah x Bl
#pragma unroll
            for (int p = 0; p < 2; p++) {
                uint32_t r0, r1, r2, r3;
                LDSM_X4(r0, r1, r2, r3,
                        blB + (wn * 32 + p * 16 + bN) * SKB + boff);
#pragma unroll
                for (int mi = 0; mi < 4; mi++) {
                    mma_bf16(acc[mi][2 * p],     Ahf[mi], r0, r1);
                    mma_bf16(acc[mi][2 * p + 1], Ahf[mi], r2, r3);
                }
            }
        }
        __syncthreads();
    }

    // epilogue: direct fp32 stores + bias
    const int g = lane >> 2;
    const int c2 = (lane & 3) * 2;
#pragma unroll
    for (int mi = 0; mi < 4; mi++) {
        const int row = m0 + wm * 64 + mi * 16 + g;
#pragma unroll
        for (int ni = 0; ni < 4; ni++) {
            const int col = n0 + wn * 32 + ni * 8 + c2;
            const float2 bb = *reinterpret_cast<const float2*>(bias + col);
            float2 v0 = { acc[mi][ni][0] + bb.x, acc[mi][ni][1] + bb.y };
            float2 v1 = { acc[mi][ni][2] + bb.x, acc[mi][ni][3] + bb.y };
            *reinterpret_cast<float2*>(C + (size_t)row * Dz + col)       = v0;
            *reinterpret_cast<float2*>(C + (size_t)(row + 8) * Dz + col) = v1;
        }
    }
}

// =====================================================================
// Flash attention (fp32, unchanged from R1 pass): O = softmax(Q K^T / 8) V
// =====================================================================
constexpr int BR = 64, BC = 64, PAD = 68;
constexpr int FLASH_SMEM = (5 * 64 * PAD + 3 * 64) * 4;   // 87808 bytes

__global__ __launch_bounds__(256, 2)
void flash_kernel(const float* __restrict__ Qg, const float* __restrict__ Kg,
                  const float* __restrict__ Vg, float* __restrict__ Og)
{
    extern __shared__ float sm[];
    float* QsT = sm;
    float* KsT = QsT + 64 * PAD;
    float* Vs  = KsT + 64 * PAD;
    float* Ss  = Vs  + 64 * PAD;
    float* PT  = Ss  + 64 * PAD;
    float* rowm = PT + 64 * PAD;
    float* rowl = rowm + 64;
    float* rowscale = rowl + 64;

    const int tid = threadIdx.x;
    const int tx  = tid & 15;
    const int ty  = tid >> 4;
    const int qt  = blockIdx.x;
    const int h   = blockIdx.y;
    const int b   = blockIdx.z;
    const float scale = 0.125f;

    const size_t base = (size_t)b * Pz * HD + (size_t)h * DKz;
    const float* Qp = Qg + base + (size_t)qt * BR * HD;

#pragma unroll
    for (int it = 0; it < 4; it++) {
        int lin = tid + it * 256;
        int r  = lin >> 4;
        int d0 = (lin & 15) * 4;
        float4 v = *reinterpret_cast<const float4*>(Qp + (size_t)r * HD + d0);
        QsT[(d0 + 0) * PAD + r] = v.x;
        QsT[(d0 + 1) * PAD + r] = v.y;
        QsT[(d0 + 2) * PAD + r] = v.z;
        QsT[(d0 + 3) * PAD + r] = v.w;
    }
    if (tid < 64) { rowm[tid] = -1e30f; rowl[tid] = 0.f; }

    float o[4][4];
#pragma unroll
    for (int i = 0; i < 4; i++)
#pragma unroll
        for (int j = 0; j < 4; j++) o[i][j] = 0.f;

    const int nTiles = Pz / BC;
    for (int t = 0; t < nTiles; t++) {
        const float* Kp = Kg + base + (size_t)t * BC * HD;
        const float* Vp = Vg + base + (size_t)t * BC * HD;

        __syncthreads();
#pragma unroll
        for (int it = 0; it < 4; it++) {
            int lin = tid + it * 256;
            int j  = lin >> 4;
            int d0 = (lin & 15) * 4;
            float4 kv = *reinterpret_cast<const float4*>(Kp + (size_t)j * HD + d0);
            KsT[(d0 + 0) * PAD + j] = kv.x;
            KsT[(d0 + 1) * PAD + j] = kv.y;
            KsT[(d0 + 2) * PAD + j] = kv.z;
            KsT[(d0 + 3) * PAD + j] = kv.w;
            float4 vv = *reinterpret_cast<const float4*>(Vp + (size_t)j * HD + d0);
            *reinterpret_cast<float4*>(Vs + j * PAD + d0) = vv;
        }
        __syncthreads();

        float s[4][4];
#pragma unroll
        for (int i = 0; i < 4; i++)
#pragma unroll
            for (int j = 0; j < 4; j++) s[i][j] = 0.f;

#pragma unroll 8
        for (int d = 0; d < 64; d++) {
            float4 qv = *reinterpret_cast<const float4*>(QsT + d * PAD + ty * 4);
            float4 kv = *reinterpret_cast<const float4*>(KsT + d * PAD + tx * 4);
            float qa[4] = {qv.x, qv.y, qv.z, qv.w};
            float ka[4] = {kv.x, kv.y, kv.z, kv.w};
#pragma unroll
            for (int i = 0; i < 4; i++)
#pragma unroll
                for (int j = 0; j < 4; j++)
                    s[i][j] = fmaf(qa[i], ka[j], s[i][j]);
        }
#pragma unroll
        for (int i = 0; i < 4; i++)
#pragma unroll
            for (int j = 0; j < 4; j++)
                Ss[(ty * 4 + i) * PAD + tx * 4 + j] = s[i][j] * scale;
        __syncthreads();

        {
            const int row = tid >> 2;
            const int cg  = tid & 3;
            float sv[16];
            float mloc = -1e30f;
#pragma unroll
            for (int jj = 0; jj < 16; jj++) {
                sv[jj] = Ss[row * PAD + cg * 16 + jj];
                mloc = fmaxf(mloc, sv[jj]);
            }
            mloc = fmaxf(mloc, __shfl_xor_sync(0xffffffffu, mloc, 1));
            mloc = fmaxf(mloc, __shfl_xor_sync(0xffffffffu, mloc, 2));
            const float mold = rowm[row];
            const float mnew = fmaxf(mold, mloc);
            float lsum = 0.f;
#pragma unroll
            for (int jj = 0; jj < 16; jj++) {
                float p = __expf(sv[jj] - mnew);
                lsum += p;
                PT[(cg * 16 + jj) * PAD + row] = p;
            }
            lsum += __shfl_xor_sync(0xffffffffu, lsum, 1);
            lsum += __shfl_xor_sync(0xffffffffu, lsum, 2);
            if (cg == 0) {
                float sc = __expf(mold - mnew);
                rowscale[row] = sc;
                rowm[row] = mnew;
                rowl[row] = rowl[row] * sc + lsum;
            }
        }
        __syncthreads();

        float sc4[4];
#pragma unroll
        for (int i = 0; i < 4; i++) sc4[i] = rowscale[ty * 4 + i];
#pragma unroll
        for (int i = 0; i < 4; i++)
#pragma unroll
            for (int j = 0; j < 4; j++) o[i][j] *= sc4[i];

#pragma unroll 8
        for (int jk = 0; jk < 64; jk++) {
            float4 pv = *reinterpret_cast<const float4*>(PT + jk * PAD + ty * 4);
            float4 vv = *reinterpret_cast<const float4*>(Vs + jk * PAD + tx * 4);
            float pa[4] = {pv.x, pv.y, pv.z, pv.w};
            float va[4] = {vv.x, vv.y, vv.z, vv.w};
#pragma unroll
            for (int i = 0; i < 4; i++)
#pragma unroll
                for (int j = 0; j < 4; j++)
                    o[i][j] = fmaf(pa[i], va[j], o[i][j]);
        }
    }

    float invl[4];
#pragma unroll
    for (int i = 0; i < 4; i++) invl[i] = 1.f / rowl[ty * 4 + i];

    float* Op = Og + base + (size_t)qt * BR * HD;
#pragma unroll
    for (int i = 0; i < 4; i++) {
        float4 w;
        w.x = o[i][0] * invl[i];
        w.y = o[i][1] * invl[i];
        w.z = o[i][2] * invl[i];
        w.w = o[i][3] * invl[i];
        *reinterpret_cast<float4*>(Op + (size_t)(ty * 4 + i) * HD + tx * 4) = w;
    }
}

// =====================================================================
// launcher
// =====================================================================
extern "C" void kernel_launch(void* const* d_in, const int* in_sizes, int n_in,
                              void* d_out, int out_size)
{
    const float* x  = (const float*)d_in[0];
    const float* Wq = (const float*)d_in[1];
    const float* bq = (const float*)d_in[2];
    const float* Wk = (const float*)d_in[3];
    const float* bk = (const float*)d_in[4];
    const float* Wv = (const float*)d_in[5];
    const float* bv = (const float*)d_in[6];
    const float* Wo = (const float*)d_in[7];
    const float* bo = (const float*)d_in[8];

    float *q, *k, *v, *rep;
    __nv_bfloat16 *xh, *xl, *wht, *wlt;
    cudaGetSymbolAddress((void**)&q,   g_Q);
    cudaGetSymbolAddress((void**)&k,   g_K);
    cudaGetSymbolAddress((void**)&v,   g_V);
    cudaGetSymbolAddress((void**)&rep, g_REP);
    cudaGetSymbolAddress((void**)&xh,  g_xh);
    cudaGetSymbolAddress((void**)&xl,  g_xl);
    cudaGetSymbolAddress((void**)&wht, g_wht);
    cudaGetSymbolAddress((void**)&wlt, g_wlt);

    cudaFuncSetAttribute(flash_kernel,
                         cudaFuncAttributeMaxDynamicSharedMemorySize, FLASH_SMEM);
    cudaFuncSetAttribute(gemm_hmma3,
                         cudaFuncAttributeMaxDynamicSharedMemorySize, GEMM_SMEM);

    const int n4 = Mrows * Dz / 4;
    const dim3 wgrid(Dz / 32, Dz / 32);
    const dim3 wblk(32, 8);
    const dim3 ggrid(Dz / 128, Mrows / 128);   // (8, 64)

    // split activations once (serves Q, K, V GEMMs)
    split_kernel<<<2048, 256>>>((const float4*)x, (__nv_bfloat162*)xh, (__nv_bfloat162*)xl, n4);

    wsplit_kernel<<<wgrid, wblk>>>(Wq, wht, wlt);
    gemm_hmma3<<<ggrid, 256, GEMM_SMEM>>>(xh, xl, wht, wlt, bq, q);
    wsplit_kernel<<<wgrid, wblk>>>(Wk, wht, wlt);
    gemm_hmma3<<<ggrid, 256, GEMM_SMEM>>>(xh, xl, wht, wlt, bk, k);
    wsplit_kernel<<<wgrid, wblk>>>(Wv, wht, wlt);
    gemm_hmma3<<<ggrid, 256, GEMM_SMEM>>>(xh, xl, wht, wlt, bv, v);

    flash_kernel<<<dim3(Pz / BR, Hz, Bz), 256, FLASH_SMEM>>>(q, k, v, rep);

    // output projection
    split_kernel<<<2048, 256>>>((const float4*)rep, (__nv_bfloat162*)xh, (__nv_bfloat162*)xl, n4);
    wsplit_kernel<<<wgrid, wblk>>>(Wo, wht, wlt);
    gemm_hmma3<<<ggrid, 256, GEMM_SMEM>>>(xh, xl, wht, wlt, bo, (float*)d_out);
}

// round 6
// speedup vs baseline: 2.9211x; 2.0067x over previous
#include <cuda_runtime.h>
#include <cuda_bf16.h>
#include <cstdint>
#include <math.h>

// Problem constants
constexpr int Bz  = 4;
constexpr int Pz  = 2048;
constexpr int Dz  = 1024;   // model dim; N and K of every GEMM
constexpr int Hz  = 16;
constexpr int DKz = 64;
constexpr int Mrows = Bz * Pz;          // 8192
constexpr int HD   = Hz * DKz;          // 1024

// ---------------- scratch (allocation-free rule: __device__ globals) -------
__device__ float g_Q  [(size_t)Mrows * HD];
__device__ float g_K  [(size_t)Mrows * HD];
__device__ float g_V  [(size_t)Mrows * HD];
__device__ float g_REP[(size_t)Mrows * HD];
__device__ __nv_bfloat16 g_xh [(size_t)Mrows * Dz];
__device__ __nv_bfloat16 g_xl [(size_t)Mrows * Dz];
__device__ __nv_bfloat16 g_wht[(size_t)Dz * Dz];
__device__ __nv_bfloat16 g_wlt[(size_t)Dz * Dz];
__device__ __nv_bfloat16 g_Kh [(size_t)Mrows * HD];
__device__ __nv_bfloat16 g_Kl [(size_t)Mrows * HD];
__device__ __nv_bfloat16 g_Vh [(size_t)Mrows * HD];
__device__ __nv_bfloat16 g_Vl [(size_t)Mrows * HD];

// =====================================================================
// baseline-PTX helpers (work on .target sm_103: no 'a' features!)
// =====================================================================
__device__ __forceinline__ uint32_t smem_u32(const void* p) {
    uint32_t a;
    asm("{ .reg .u64 t; cvta.to.shared.u64 t, %1; cvt.u32.u64 %0, t; }"
        : "=r"(a) : "l"(p));
    return a;
}
#define LDSM_X4(r0, r1, r2, r3, addr) \
    asm volatile("ldmatrix.sync.aligned.m8n8.x4.shared.b16 {%0,%1,%2,%3}, [%4];" \
                 : "=r"(r0), "=r"(r1), "=r"(r2), "=r"(r3) : "r"(addr))
#define LDSM_X4_T(r0, r1, r2, r3, addr) \
    asm volatile("ldmatrix.sync.aligned.m8n8.x4.trans.shared.b16 {%0,%1,%2,%3}, [%4];" \
                 : "=r"(r0), "=r"(r1), "=r"(r2), "=r"(r3) : "r"(addr))
#define CP_ASYNC16(dst, src) \
    asm volatile("cp.async.ca.shared.global [%0], [%1], 16;" :: "r"(dst), "l"(src))
#define CP_COMMIT() asm volatile("cp.async.commit_group;" ::: "memory")
#define CP_WAIT1()  asm volatile("cp.async.wait_group 1;" ::: "memory")
#define CP_WAIT0()  asm volatile("cp.async.wait_group 0;" ::: "memory")

__device__ __forceinline__ void mma_bf16(float* c, const uint32_t a[4],
                                         uint32_t b0, uint32_t b1) {
    asm volatile(
        "mma.sync.aligned.m16n8k16.row.col.f32.bf16.bf16.f32 "
        "{%0,%1,%2,%3}, {%4,%5,%6,%7}, {%8,%9}, {%0,%1,%2,%3};"
        : "+f"(c[0]), "+f"(c[1]), "+f"(c[2]), "+f"(c[3])
        : "r"(a[0]), "r"(a[1]), "r"(a[2]), "r"(a[3]), "r"(b0), "r"(b1));
}

// fast exp on FMA pipe (avoids the chip-wide MUFU floor)
__device__ __forceinline__ float fast_exp(float x) {
    float t = fmaxf(x * 1.4426950408889634f, -126.0f);
    float r = t + 12582912.0f;                 // round-to-nearest-int trick
    float i = r - 12582912.0f;
    float f = t - i;
    float p = 1.3333558e-3f;
    p = fmaf(p, f, 9.6181291e-3f);
    p = fmaf(p, f, 5.5504109e-2f);
    p = fmaf(p, f, 2.4022651e-1f);
    p = fmaf(p, f, 6.9314718e-1f);
    p = fmaf(p, f, 1.0f);
    float s = __int_as_float(((int)i + 127) << 23);   // 2^i
    return p * s;
}

__device__ __forceinline__ void split2(float x, __nv_bfloat16& h, __nv_bfloat16& l) {
    h = __float2bfloat16_rn(x);
    l = __float2bfloat16_rn(x - __bfloat162float(h));
}
__device__ __forceinline__ uint32_t pk2(__nv_bfloat16 a, __nv_bfloat16 b) {
    __nv_bfloat162 v; v.x = a; v.y = b;
    return reinterpret_cast<uint32_t&>(v);
}
__device__ __forceinline__ void splitpack(float a, float b, uint32_t& hi, uint32_t& lo) {
    __nv_bfloat16 ah, al, bh, bl;
    split2(a, ah, al); split2(b, bh, bl);
    hi = pk2(ah, bh); lo = pk2(al, bl);
}

// =====================================================================
// split kernels
// =====================================================================
__global__ void split_kernel(const float4* __restrict__ src,
                             __nv_bfloat162* __restrict__ hi,
                             __nv_bfloat162* __restrict__ lo, int n4)
{
    int i = blockIdx.x * blockDim.x + threadIdx.x;
    int stride = gridDim.x * blockDim.x;
    for (; i < n4; i += stride) {
        float4 v = src[i];
        __nv_bfloat16 h0, h1, h2, h3, l0, l1, l2, l3;
        split2(v.x, h0, l0); split2(v.y, h1, l1);
        split2(v.z, h2, l2); split2(v.w, h3, l3);
        hi[2 * i]     = __halves2bfloat162(h0, h1);
        hi[2 * i + 1] = __halves2bfloat162(h2, h3);
        lo[2 * i]     = __halves2bfloat162(l0, l1);
        lo[2 * i + 1] = __halves2bfloat162(l2, l3);
    }
}

__global__ void wsplit_kernel(const float* __restrict__ W,
                              __nv_bfloat16* __restrict__ WhT,
                              __nv_bfloat16* __restrict__ WlT)
{
    __shared__ float s[32][33];
    const int n0 = blockIdx.x * 32, k0 = blockIdx.y * 32;
    const int tx = threadIdx.x, ty = threadIdx.y;   // (32, 8)
#pragma unroll
    for (int i = 0; i < 4; i++)
        s[ty + i * 8][tx] = W[(size_t)(k0 + ty + i * 8) * Dz + n0 + tx];
    __syncthreads();
#pragma unroll
    for (int i = 0; i < 4; i++) {
        const int n = n0 + ty + i * 8;
        const int k = k0 + tx;
        __nv_bfloat16 h, l;
        split2(s[tx][ty + i * 8], h, l);
        WhT[(size_t)n * Dz + k] = h;
        WlT[(size_t)n * Dz + k] = l;
    }
}

// =====================================================================
// HMMA split-bf16 GEMM (unchanged from R4 pass)
// =====================================================================
constexpr int SKB   = 80;
constexpr int TILEB = 128 * SKB;
constexpr int BUFB  = 4 * TILEB;
constexpr int GEMM_SMEM = 2 * BUFB;        // 81920

__global__ __launch_bounds__(256)
void gemm_hmma3(const __nv_bfloat16* __restrict__ Ah, const __nv_bfloat16* __restrict__ Al,
                const __nv_bfloat16* __restrict__ Bh, const __nv_bfloat16* __restrict__ Bl,
                const float* __restrict__ bias, float* __restrict__ C)
{
    extern __shared__ char smem[];
    const uint32_t sbase = smem_u32(smem);
    const int tid  = threadIdx.x;
    const int lane = tid & 31;
    const int wid  = tid >> 5;
    const int wm   = wid >> 2;
    const int wn   = wid & 3;
    const int m0 = blockIdx.y * 128;
    const int n0 = blockIdx.x * 128;

    const __nv_bfloat16* srcs[4] = {
        Ah + (size_t)m0 * Dz, Al + (size_t)m0 * Dz,
        Bh + (size_t)n0 * Dz, Bl + (size_t)n0 * Dz };

    float acc[4][4][4];
#pragma unroll
    for (int mi = 0; mi < 4; mi++)
#pragma unroll
        for (int ni = 0; ni < 4; ni++)
#pragma unroll
            for (int r = 0; r < 4; r++) acc[mi][ni][r] = 0.f;

    auto issue = [&](int t, int b) {
#pragma unroll
        for (int p = 0; p < 4; p++) {
            const __nv_bfloat16* s = srcs[p] + t * 32;
            const uint32_t dT = sbase + b * BUFB + p * TILEB;
#pragma unroll
            for (int i = 0; i < 2; i++) {
                int lin = tid + i * 256;
                int row = lin >> 2, kg = lin & 3;
                CP_ASYNC16(dT + row * SKB + kg * 16,
                           s + (size_t)row * Dz + kg * 8);
            }
        }
        CP_COMMIT();
    };

    const uint32_t aRow = lane & 15;
    const uint32_t aK   = (lane >> 4) * 8;
    const uint32_t bN   = ((lane >> 4) & 1) * 8 + (lane & 7);
    const uint32_t bK   = ((lane >> 3) & 1) * 8;

    issue(0, 0);
    const int nk = Dz / 32;
    for (int t = 0; t < nk; t++) {
        if (t + 1 < nk) { issue(t + 1, (t + 1) & 1); CP_WAIT1(); }
        else            { CP_WAIT0(); }
        __syncthreads();

        const uint32_t bb  = sbase + (t & 1) * BUFB;
        const uint32_t ahB = bb, alB = bb + TILEB;
        const uint32_t bhB = bb + 2 * TILEB, blB = bb + 3 * TILEB;

#pragma unroll
        for (int ks = 0; ks < 32; ks += 16) {
            const uint32_t aoff = (aK + ks) * 2;
            const uint32_t boff = (bK + ks) * 2;

            uint32_t Ahf[4][4], Bhf[4][2];
#pragma unroll
            for (int p = 0; p < 2; p++) {
                uint32_t r0, r1, r2, r3;
                LDSM_X4(r0, r1, r2, r3,
                        bhB + (wn * 32 + p * 16 + bN) * SKB + boff);
                Bhf[2 * p][0] = r0; Bhf[2 * p][1] = r1;
                Bhf[2 * p + 1][0] = r2; Bhf[2 * p + 1][1] = r3;
            }
#pragma unroll
            for (int mi = 0; mi < 4; mi++)
                LDSM_X4(Ahf[mi][0], Ahf[mi][1], Ahf[mi][2], Ahf[mi][3],
                        ahB + (wm * 64 + mi * 16 + aRow) * SKB + aoff);
#pragma unroll
            for (int mi = 0; mi < 4; mi++)
#pragma unroll
                for (int ni = 0; ni < 4; ni++)
                    mma_bf16(acc[mi][ni], Ahf[mi], Bhf[ni][0], Bhf[ni][1]);
#pragma unroll
            for (int mi = 0; mi < 4; mi++) {
                uint32_t Alf[4];
                LDSM_X4(Alf[0], Alf[1], Alf[2], Alf[3],
                        alB + (wm * 64 + mi * 16 + aRow) * SKB + aoff);
#pragma unroll
                for (int ni = 0; ni < 4; ni++)
                    mma_bf16(acc[mi][ni], Alf, Bhf[ni][0], Bhf[ni][1]);
            }
#pragma unroll
            for (int p = 0; p < 2; p++) {
                uint32_t r0, r1, r2, r3;
                LDSM_X4(r0, r1, r2, r3,
                        blB + (wn * 32 + p * 16 + bN) * SKB + boff);
#pragma unroll
                for (int mi = 0; mi < 4; mi++) {
                    mma_bf16(acc[mi][2 * p],     Ahf[mi], r0, r1);
                    mma_bf16(acc[mi][2 * p + 1], Ahf[mi], r2, r3);
                }
            }
        }
        __syncthreads();
    }

    const int g = lane >> 2;
    const int c2 = (lane & 3) * 2;
#pragma unroll
    for (int mi = 0; mi < 4; mi++) {
        const int row = m0 + wm * 64 + mi * 16 + g;
#pragma unroll
        for (int ni = 0; ni < 4; ni++) {
            const int col = n0 + wn * 32 + ni * 8 + c2;
            const float2 bb = *reinterpret_cast<const float2*>(bias + col);
            float2 v0 = { acc[mi][ni][0] + bb.x, acc[mi][ni][1] + bb.y };
            float2 v1 = { acc[mi][ni][2] + bb.x, acc[mi][ni][3] + bb.y };
            *reinterpret_cast<float2*>(C + (size_t)row * Dz + col)       = v0;
            *reinterpret_cast<float2*>(C + (size_t)(row + 8) * Dz + col) = v1;
        }
    }
}

// =====================================================================
// HMMA flash attention: BR=128 rows/CTA, BC=64, split-bf16 on both GEMMs.
// Q in registers (split once); K/V pre-split bf16 in gmem, cp.async double
// buffered; S C-frag -> P A-frag with zero data movement; exp on FMA pipe.
// =====================================================================
constexpr int FSTR = 144;                          // smem row stride bytes
constexpr int FTILE = 64 * FSTR;                   // 9216
constexpr int FBUF  = 4 * FTILE;                   // 36864
constexpr int FLASH_SMEM = 2 * FBUF;               // 73728

__global__ __launch_bounds__(256)
void flash_hmma(const float* __restrict__ Qf,
                const __nv_bfloat16* __restrict__ Kh, const __nv_bfloat16* __restrict__ Kl,
                const __nv_bfloat16* __restrict__ Vh, const __nv_bfloat16* __restrict__ Vl,
                float* __restrict__ Og)
{
    extern __shared__ char smem[];
    const uint32_t sbase = smem_u32(smem);
    const int tid = threadIdx.x, lane = tid & 31, wid = tid >> 5;
    const int g = lane >> 2, t4 = lane & 3;
    const int qt = blockIdx.x, h = blockIdx.y, b = blockIdx.z;
    const size_t base = (size_t)b * Pz * HD + (size_t)h * DKz;

    // ---- Q fragments: load fp32, fold scale (exact 2^-3), split hi/lo ----
    uint32_t Qh[4][4], Ql[4][4];
    {
        const float* Qp = Qf + base + (size_t)(qt * 128 + wid * 16) * HD;
        const int qc = 2 * t4;
#pragma unroll
        for (int s = 0; s < 4; s++) {
            float2 v00 = *reinterpret_cast<const float2*>(Qp + (size_t)g * HD + s * 16 + qc);
            float2 v10 = *reinterpret_cast<const float2*>(Qp + (size_t)(g + 8) * HD + s * 16 + qc);
            float2 v01 = *reinterpret_cast<const float2*>(Qp + (size_t)g * HD + s * 16 + 8 + qc);
            float2 v11 = *reinterpret_cast<const float2*>(Qp + (size_t)(g + 8) * HD + s * 16 + 8 + qc);
            splitpack(v00.x * 0.125f, v00.y * 0.125f, Qh[s][0], Ql[s][0]);
            splitpack(v10.x * 0.125f, v10.y * 0.125f, Qh[s][1], Ql[s][1]);
            splitpack(v01.x * 0.125f, v01.y * 0.125f, Qh[s][2], Ql[s][2]);
            splitpack(v11.x * 0.125f, v11.y * 0.125f, Qh[s][3], Ql[s][3]);
        }
    }

    const __nv_bfloat16* srcs[4] = { Kh + base, Kl + base, Vh + base, Vl + base };

    auto issue = [&](int tt, int bf) {
#pragma unroll
        for (int p = 0; p < 4; p++) {
            const __nv_bfloat16* s = srcs[p] + (size_t)(tt * 64) * HD;
            const uint32_t dT = sbase + bf * FBUF + p * FTILE;
#pragma unroll
            for (int i = 0; i < 2; i++) {
                int lin = tid + i * 256;           // 0..511
                int row = lin >> 3, ch = lin & 7;
                CP_ASYNC16(dT + row * FSTR + ch * 16,
                           s + (size_t)row * HD + ch * 8);
            }
        }
        CP_COMMIT();
    };

    // ldmatrix lane address components
    const uint32_t bN = ((lane >> 4) & 1) * 8 + (lane & 7);   // K non-trans
    const uint32_t bK = ((lane >> 3) & 1) * 8;
    const uint32_t part = lane >> 3;                           // V trans
    const uint32_t vRow = (part & 1) * 8 + (lane & 7);
    const uint32_t vCol = (part >> 1) * 8;

    float O[8][4];
#pragma unroll
    for (int nt = 0; nt < 8; nt++)
#pragma unroll
        for (int r = 0; r < 4; r++) O[nt][r] = 0.f;
    float m0 = -1e30f, m1 = -1e30f, l0 = 0.f, l1 = 0.f;

    issue(0, 0);
    const int nT = Pz / 64;                         // 32
    for (int t = 0; t < nT; t++) {
        if (t + 1 < nT) { issue(t + 1, (t + 1) & 1); CP_WAIT1(); }
        else            { CP_WAIT0(); }
        __syncthreads();

        const uint32_t bb = sbase + (t & 1) * FBUF;
        const uint32_t khB = bb, klB = bb + FTILE;
        const uint32_t vhB = bb + 2 * FTILE, vlB = bb + 3 * FTILE;

        // ---- S = (Qh+Ql)(Kh+Kl)^T, 3 terms ----
        float Sa[8][4];
#pragma unroll
        for (int nt = 0; nt < 8; nt++)
#pragma unroll
            for (int r = 0; r < 4; r++) Sa[nt][r] = 0.f;

#pragma unroll
        for (int s = 0; s < 4; s++) {
            uint32_t B[8][2];
#pragma unroll
            for (int p = 0; p < 4; p++) {
                uint32_t r0, r1, r2, r3;
                LDSM_X4(r0, r1, r2, r3, khB + (p * 16 + bN) * FSTR + (bK + s * 16) * 2);
                B[2 * p][0] = r0; B[2 * p][1] = r1;
                B[2 * p + 1][0] = r2; B[2 * p + 1][1] = r3;
            }
#pragma unroll
            for (int nt = 0; nt < 8; nt++) mma_bf16(Sa[nt], Qh[s], B[nt][0], B[nt][1]);
#pragma unroll
            for (int nt = 0; nt < 8; nt++) mma_bf16(Sa[nt], Ql[s], B[nt][0], B[nt][1]);
#pragma unroll
            for (int p = 0; p < 4; p++) {
                uint32_t r0, r1, r2, r3;
                LDSM_X4(r0, r1, r2, r3, klB + (p * 16 + bN) * FSTR + (bK + s * 16) * 2);
                B[2 * p][0] = r0; B[2 * p][1] = r1;
                B[2 * p + 1][0] = r2; B[2 * p + 1][1] = r3;
            }
#pragma unroll
            for (int nt = 0; nt < 8; nt++) mma_bf16(Sa[nt], Qh[s], B[nt][0], B[nt][1]);
        }

        // ---- online softmax on fragments (rows g and g+8) ----
        float ml0 = -1e30f, ml1 = -1e30f;
#pragma unroll
        for (int nt = 0; nt < 8; nt++) {
            ml0 = fmaxf(ml0, fmaxf(Sa[nt][0], Sa[nt][1]));
            ml1 = fmaxf(ml1, fmaxf(Sa[nt][2], Sa[nt][3]));
        }
        ml0 = fmaxf(ml0, __shfl_xor_sync(0xffffffffu, ml0, 1));
        ml0 = fmaxf(ml0, __shfl_xor_sync(0xffffffffu, ml0, 2));
        ml1 = fmaxf(ml1, __shfl_xor_sync(0xffffffffu, ml1, 1));
        ml1 = fmaxf(ml1, __shfl_xor_sync(0xffffffffu, ml1, 2));
        const float mn0 = fmaxf(m0, ml0), mn1 = fmaxf(m1, ml1);
        const float sc0 = fast_exp(m0 - mn0), sc1 = fast_exp(m1 - mn1);
        m0 = mn0; m1 = mn1;

        float ps0 = 0.f, ps1 = 0.f;
#pragma unroll
        for (int nt = 0; nt < 8; nt++) {
            Sa[nt][0] = fast_exp(Sa[nt][0] - mn0);
            Sa[nt][1] = fast_exp(Sa[nt][1] - mn0);
            Sa[nt][2] = fast_exp(Sa[nt][2] - mn1);
            Sa[nt][3] = fast_exp(Sa[nt][3] - mn1);
            ps0 += Sa[nt][0] + Sa[nt][1];
            ps1 += Sa[nt][2] + Sa[nt][3];
        }
        ps0 += __shfl_xor_sync(0xffffffffu, ps0, 1);
        ps0 += __shfl_xor_sync(0xffffffffu, ps0, 2);
        ps1 += __shfl_xor_sync(0xffffffffu, ps1, 1);
        ps1 += __shfl_xor_sync(0xffffffffu, ps1, 2);
        l0 = l0 * sc0 + ps0;
        l1 = l1 * sc1 + ps1;

#pragma unroll
        for (int nt = 0; nt < 8; nt++) {
            O[nt][0] *= sc0; O[nt][1] *= sc0;
            O[nt][2] *= sc1; O[nt][3] *= sc1;
        }

        // ---- P fragments: S C-frag -> A-frag, split hi/lo ----
        uint32_t Ph[4][4], Pl[4][4];
#pragma unroll
        for (int s = 0; s < 4; s++) {
            splitpack(Sa[2 * s][0],     Sa[2 * s][1],     Ph[s][0], Pl[s][0]);
            splitpack(Sa[2 * s][2],     Sa[2 * s][3],     Ph[s][1], Pl[s][1]);
            splitpack(Sa[2 * s + 1][0], Sa[2 * s + 1][1], Ph[s][2], Pl[s][2]);
            splitpack(Sa[2 * s + 1][2], Sa[2 * s + 1][3], Ph[s][3], Pl[s][3]);
        }

        // ---- O += (Ph+Pl)(Vh+Vl), 3 terms ----
#pragma unroll
        for (int s = 0; s < 4; s++) {
            uint32_t B[8][2];
#pragma unroll
            for (int p = 0; p < 4; p++) {
                uint32_t r0, r1, r2, r3;
                LDSM_X4_T(r0, r1, r2, r3,
                          vhB + (s * 16 + vRow) * FSTR + (p * 16 + vCol) * 2);
                B[2 * p][0] = r0; B[2 * p][1] = r1;
                B[2 * p + 1][0] = r2; B[2 * p + 1][1] = r3;
            }
#pragma unroll
            for (int nt = 0; nt < 8; nt++) mma_bf16(O[nt], Ph[s], B[nt][0], B[nt][1]);
#pragma unroll
            for (int nt = 0; nt < 8; nt++) mma_bf16(O[nt], Pl[s], B[nt][0], B[nt][1]);
#pragma unroll
            for (int p = 0; p < 4; p++) {
                uint32_t r0, r1, r2, r3;
                LDSM_X4_T(r0, r1, r2, r3,
                          vlB + (s * 16 + vRow) * FSTR + (p * 16 + vCol) * 2);
                B[2 * p][0] = r0; B[2 * p][1] = r1;
                B[2 * p + 1][0] = r2; B[2 * p + 1][1] = r3;
            }
#pragma unroll
            for (int nt = 0; nt < 8; nt++) mma_bf16(O[nt], Ph[s], B[nt][0], B[nt][1]);
        }
        __syncthreads();
    }

    // ---- finalize ----
    const float inv0 = 1.f / l0, inv1 = 1.f / l1;
    float* Op = Og + base + (size_t)(qt * 128 + wid * 16) * HD;
    const int qc = 2 * t4;
#pragma unroll
    for (int nt = 0; nt < 8; nt++) {
        const int col = nt * 8 + qc;
        float2 v0 = { O[nt][0] * inv0, O[nt][1] * inv0 };
        float2 v1 = { O[nt][2] * inv1, O[nt][3] * inv1 };
        *reinterpret_cast<float2*>(Op + (size_t)g * HD + col)       = v0;
        *reinterpret_cast<float2*>(Op + (size_t)(g + 8) * HD + col) = v1;
    }
}

// =====================================================================
// launcher
// =====================================================================
extern "C" void kernel_launch(void* const* d_in, const int* in_sizes, int n_in,
                              void* d_out, int out_size)
{
    const float* x  = (const float*)d_in[0];
    const float* Wq = (const float*)d_in[1];
    const float* bq = (const float*)d_in[2];
    const float* Wk = (const float*)d_in[3];
    const float* bk = (const float*)d_in[4];
    const float* Wv = (const float*)d_in[5];
    const float* bv = (const float*)d_in[6];
    const float* Wo = (const float*)d_in[7];
    const float* bo = (const float*)d_in[8];

    float *q, *k, *v, *rep;
    __nv_bfloat16 *xh, *xl, *wht, *wlt, *kh, *kl, *vh, *vl;
    cudaGetSymbolAddress((void**)&q,   g_Q);
    cudaGetSymbolAddress((void**)&k,   g_K);
    cudaGetSymbolAddress((void**)&v,   g_V);
    cudaGetSymbolAddress((void**)&rep, g_REP);
    cudaGetSymbolAddress((void**)&xh,  g_xh);
    cudaGetSymbolAddress((void**)&xl,  g_xl);
    cudaGetSymbolAddress((void**)&wht, g_wht);
    cudaGetSymbolAddress((void**)&wlt, g_wlt);
    cudaGetSymbolAddress((void**)&kh,  g_Kh);
    cudaGetSymbolAddress((void**)&kl,  g_Kl);
    cudaGetSymbolAddress((void**)&vh,  g_Vh);
    cudaGetSymbolAddress((void**)&vl,  g_Vl);

    cudaFuncSetAttribute(flash_hmma,
                         cudaFuncAttributeMaxDynamicSharedMemorySize, FLASH_SMEM);
    cudaFuncSetAttribute(gemm_hmma3,
                         cudaFuncAttributeMaxDynamicSharedMemorySize, GEMM_SMEM);

    const int n4 = Mrows * Dz / 4;
    const dim3 wgrid(Dz / 32, Dz / 32);
    const dim3 wblk(32, 8);
    const dim3 ggrid(Dz / 128, Mrows / 128);

    split_kernel<<<2048, 256>>>((const float4*)x, (__nv_bfloat162*)xh, (__nv_bfloat162*)xl, n4);

    wsplit_kernel<<<wgrid, wblk>>>(Wq, wht, wlt);
    gemm_hmma3<<<ggrid, 256, GEMM_SMEM>>>(xh, xl, wht, wlt, bq, q);
    wsplit_kernel<<<wgrid, wblk>>>(Wk, wht, wlt);
    gemm_hmma3<<<ggrid, 256, GEMM_SMEM>>>(xh, xl, wht, wlt, bk, k);
    wsplit_kernel<<<wgrid, wblk>>>(Wv, wht, wlt);
    gemm_hmma3<<<ggrid, 256, GEMM_SMEM>>>(xh, xl, wht, wlt, bv, v);

    // pre-split K, V for the attention MMAs
    split_kernel<<<2048, 256>>>((const float4*)k, (__nv_bfloat162*)kh, (__nv_bfloat162*)kl, n4);
    split_kernel<<<2048, 256>>>((const float4*)v, (__nv_bfloat162*)vh, (__nv_bfloat162*)vl, n4);

    flash_hmma<<<dim3(Pz / 128, Hz, Bz), 256, FLASH_SMEM>>>(q, kh, kl, vh, vl, rep);

    split_kernel<<<2048, 256>>>((const float4*)rep, (__nv_bfloat162*)xh, (__nv_bfloat162*)xl, n4);
    wsplit_kernel<<<wgrid, wblk>>>(Wo, wht, wlt);
    gemm_hmma3<<<ggrid, 256, GEMM_SMEM>>>(xh, xl, wht, wlt, bo, (float*)d_out);
}

// round 8
// speedup vs baseline: 2.9408x; 1.0068x over previous
#include <cuda_runtime.h>
#include <cuda_bf16.h>
#include <cstdint>
#include <math.h>

// Problem constants
constexpr int Bz  = 4;
constexpr int Pz  = 2048;
constexpr int Dz  = 1024;
constexpr int Hz  = 16;
constexpr int DKz = 64;
constexpr int Mrows = Bz * Pz;          // 8192
constexpr int HD   = Hz * DKz;          // 1024

// ---------------- scratch (allocation-free rule: __device__ globals) -------
__device__ __nv_bfloat16 g_xh [(size_t)Mrows * Dz];
__device__ __nv_bfloat16 g_xl [(size_t)Mrows * Dz];
__device__ __nv_bfloat16 g_wht[(size_t)3 * Dz * Dz];   // [3072,1024] or Wo in [0,1024)
__device__ __nv_bfloat16 g_wlt[(size_t)3 * Dz * Dz];
__device__ __nv_bfloat16 g_Qh [(size_t)Mrows * HD];
__device__ __nv_bfloat16 g_Ql [(size_t)Mrows * HD];
__device__ __nv_bfloat16 g_Kh [(size_t)Mrows * HD];
__device__ __nv_bfloat16 g_Kl [(size_t)Mrows * HD];
__device__ __nv_bfloat16 g_Vh [(size_t)Mrows * HD];
__device__ __nv_bfloat16 g_Vl [(size_t)Mrows * HD];
__device__ __nv_bfloat16 g_Rh [(size_t)Mrows * HD];
__device__ __nv_bfloat16 g_Rl [(size_t)Mrows * HD];

// =====================================================================
// baseline-PTX helpers (work on .target sm_103: no 'a' features!)
// =====================================================================
__device__ __forceinline__ uint32_t smem_u32(const void* p) {
    uint32_t a;
    asm("{ .reg .u64 t; cvta.to.shared.u64 t, %1; cvt.u32.u64 %0, t; }"
        : "=r"(a) : "l"(p));
    return a;
}
#define LDSM_X4(r0, r1, r2, r3, addr) \
    asm volatile("ldmatrix.sync.aligned.m8n8.x4.shared.b16 {%0,%1,%2,%3}, [%4];" \
                 : "=r"(r0), "=r"(r1), "=r"(r2), "=r"(r3) : "r"(addr))
#define LDSM_X4_T(r0, r1, r2, r3, addr) \
    asm volatile("ldmatrix.sync.aligned.m8n8.x4.trans.shared.b16 {%0,%1,%2,%3}, [%4];" \
                 : "=r"(r0), "=r"(r1), "=r"(r2), "=r"(r3) : "r"(addr))
#define CP_ASYNC16(dst, src) \
    asm volatile("cp.async.ca.shared.global [%0], [%1], 16;" :: "r"(dst), "l"(src))
#define CP_COMMIT() asm volatile("cp.async.commit_group;" ::: "memory")
#define CP_WAIT1()  asm volatile("cp.async.wait_group 1;" ::: "memory")
#define CP_WAIT0()  asm volatile("cp.async.wait_group 0;" ::: "memory")

__device__ __forceinline__ void mma_bf16(float* c, const uint32_t a[4],
                                         uint32_t b0, uint32_t b1) {
    asm volatile(
        "mma.sync.aligned.m16n8k16.row.col.f32.bf16.bf16.f32 "
        "{%0,%1,%2,%3}, {%4,%5,%6,%7}, {%8,%9}, {%0,%1,%2,%3};"
        : "+f"(c[0]), "+f"(c[1]), "+f"(c[2]), "+f"(c[3])
        : "r"(a[0]), "r"(a[1]), "r"(a[2]), "r"(a[3]), "r"(b0), "r"(b1));
}

// fast exp on FMA pipe (avoids the chip-wide MUFU floor)
__device__ __forceinline__ float fast_exp(float x) {
    float t = fmaxf(x * 1.4426950408889634f, -126.0f);
    float r = t + 12582912.0f;
    float i = r - 12582912.0f;
    float f = t - i;
    float p = 1.3333558e-3f;
    p = fmaf(p, f, 9.6181291e-3f);
    p = fmaf(p, f, 5.5504109e-2f);
    p = fmaf(p, f, 2.4022651e-1f);
    p = fmaf(p, f, 6.9314718e-1f);
    p = fmaf(p, f, 1.0f);
    float s = __int_as_float(((int)i + 127) << 23);
    return p * s;
}

__device__ __forceinline__ void split2(float x, __nv_bfloat16& h, __nv_bfloat16& l) {
    h = __float2bfloat16_rn(x);
    l = __float2bfloat16_rn(x - __bfloat162float(h));
}
__device__ __forceinline__ uint32_t pk2(__nv_bfloat16 a, __nv_bfloat16 b) {
    __nv_bfloat162 v; v.x = a; v.y = b;
    return reinterpret_cast<uint32_t&>(v);
}
__device__ __forceinline__ void splitpack(float a, float b, uint32_t& hi, uint32_t& lo) {
    __nv_bfloat16 ah, al, bh, bl;
    split2(a, ah, al); split2(b, bh, bl);
    hi = pk2(ah, bh); lo = pk2(al, bl);
}

// =====================================================================
// input split kernels
// =====================================================================
__global__ void split_kernel(const float4* __restrict__ src,
                             __nv_bfloat162* __restrict__ hi,
                             __nv_bfloat162* __restrict__ lo, int n4)
{
    int i = blockIdx.x * blockDim.x + threadIdx.x;
    int stride = gridDim.x * blockDim.x;
    for (; i < n4; i += stride) {
        float4 v = src[i];
        __nv_bfloat16 h0, h1, h2, h3, l0, l1, l2, l3;
        split2(v.x, h0, l0); split2(v.y, h1, l1);
        split2(v.z, h2, l2); split2(v.w, h3, l3);
        hi[2 * i]     = __halves2bfloat162(h0, h1);
        hi[2 * i + 1] = __halves2bfloat162(h2, h3);
        lo[2 * i]     = __halves2bfloat162(l0, l1);
        lo[2 * i + 1] = __halves2bfloat162(l2, l3);
    }
}

__global__ void wsplit_kernel(const float* __restrict__ W,
                              __nv_bfloat16* __restrict__ WhT,
                              __nv_bfloat16* __restrict__ WlT)
{
    __shared__ float s[32][33];
    const int n0 = blockIdx.x * 32, k0 = blockIdx.y * 32;
    const int tx = threadIdx.x, ty = threadIdx.y;   // (32, 8)
#pragma unroll
    for (int i = 0; i < 4; i++)
        s[ty + i * 8][tx] = W[(size_t)(k0 + ty + i * 8) * Dz + n0 + tx];
    __syncthreads();
#pragma unroll
    for (int i = 0; i < 4; i++) {
        const int n = n0 + ty + i * 8;
        const int k = k0 + tx;
        __nv_bfloat16 h, l;
        split2(s[tx][ty + i * 8], h, l);
        WhT[(size_t)n * Dz + k] = h;
        WlT[(size_t)n * Dz + k] = l;
    }
}

// =====================================================================
// HMMA split-bf16 GEMM, CTA 128(M)x256(N), BK=32, 8 warps of 64x64.
// EPI=0: QKV fused epilogue -> bf16 hi/lo per segment (Q scaled 1/8)
// EPI=1: fp32 out + bias (output projection)
// =====================================================================
constexpr int SKB  = 80;                   // smem row stride bytes
constexpr int TA   = 128 * SKB;            // 10240
constexpr int TB   = 256 * SKB;            // 20480
constexpr int WBUF = 2 * TA + 2 * TB;      // 61440
constexpr int GEMM_SMEM = 2 * WBUF;        // 122880

template<int EPI>
__global__ __launch_bounds__(256)
void gemm_wide(const __nv_bfloat16* __restrict__ Ah, const __nv_bfloat16* __restrict__ Al,
               const __nv_bfloat16* __restrict__ Bh, const __nv_bfloat16* __restrict__ Bl,
               const float* __restrict__ b0p, const float* __restrict__ b1p,
               const float* __restrict__ b2p,
               float* __restrict__ Cf,
               __nv_bfloat16* __restrict__ QH, __nv_bfloat16* __restrict__ QL,
               __nv_bfloat16* __restrict__ KH, __nv_bfloat16* __restrict__ KL,
               __nv_bfloat16* __restrict__ VH, __nv_bfloat16* __restrict__ VL)
{
    extern __shared__ char smem[];
    const uint32_t sbase = smem_u32(smem);
    const int tid  = threadIdx.x;
    const int lane = tid & 31;
    const int wid  = tid >> 5;
    const int wm   = wid >> 2;       // 0..1
    const int wn   = wid & 3;        // 0..3
    const int m0 = blockIdx.y * 128;
    const int n0 = blockIdx.x * 256;

    const __nv_bfloat16* srcA[2] = { Ah + (size_t)m0 * Dz, Al + (size_t)m0 * Dz };
    const __nv_bfloat16* srcB[2] = { Bh + (size_t)n0 * Dz, Bl + (size_t)n0 * Dz };

    float acc[4][8][4];
#pragma unroll
    for (int mi = 0; mi < 4; mi++)
#pragma unroll
        for (int ni = 0; ni < 8; ni++)
#pragma unroll
            for (int r = 0; r < 4; r++) acc[mi][ni][r] = 0.f;

    auto issue = [&](int t, int b) {
        const uint32_t bb = sbase + b * WBUF;
#pragma unroll
        for (int p = 0; p < 2; p++) {
            const __nv_bfloat16* s = srcA[p] + t * 32;
            const uint32_t dT = bb + p * TA;
#pragma unroll
            for (int i = 0; i < 2; i++) {
                int lin = tid + i * 256;           // 0..511
                int row = lin >> 2, kg = lin & 3;
                CP_ASYNC16(dT + row * SKB + kg * 16, s + (size_t)row * Dz + kg * 8);
            }
        }
#pragma unroll
        for (int p = 0; p < 2; p++) {
            const __nv_bfloat16* s = srcB[p] + t * 32;
            const uint32_t dT = bb + 2 * TA + p * TB;
#pragma unroll
            for (int i = 0; i < 4; i++) {
                int lin = tid + i * 256;           // 0..1023
                int row = lin >> 2, kg = lin & 3;
                CP_ASYNC16(dT + row * SKB + kg * 16, s + (size_t)row * Dz + kg * 8);
            }
        }
        CP_COMMIT();
    };

    const uint32_t aRow = lane & 15;
    const uint32_t aK   = (lane >> 4) * 8;
    const uint32_t bN   = ((lane >> 4) & 1) * 8 + (lane & 7);
    const uint32_t bK   = ((lane >> 3) & 1) * 8;

    issue(0, 0);
    const int nk = Dz / 32;                        // 32
    for (int t = 0; t < nk; t++) {
        if (t + 1 < nk) { issue(t + 1, (t + 1) & 1); CP_WAIT1(); }
        else            { CP_WAIT0(); }
        __syncthreads();

        const uint32_t bb  = sbase + (t & 1) * WBUF;
        const uint32_t ahB = bb, alB = bb + TA;
        const uint32_t bhB = bb + 2 * TA, blB = bb + 2 * TA + TB;

#pragma unroll
        for (int ks = 0; ks < 32; ks += 16) {
            const uint32_t aoff = (aK + ks) * 2;
            const uint32_t boff = (bK + ks) * 2;

            uint32_t Ahf[4][4], Bhf[8][2];
#pragma unroll
            for (int p = 0; p < 4; p++) {
                uint32_t r0, r1, r2, r3;
                LDSM_X4(r0, r1, r2, r3, bhB + (wn * 64 + p * 16 + bN) * SKB + boff);
                Bhf[2 * p][0] = r0; Bhf[2 * p][1] = r1;
                Bhf[2 * p + 1][0] = r2; Bhf[2 * p + 1][1] = r3;
            }
#pragma unroll
            for (int mi = 0; mi < 4; mi++)
                LDSM_X4(Ahf[mi][0], Ahf[mi][1], Ahf[mi][2], Ahf[mi][3],
                        ahB + (wm * 64 + mi * 16 + aRow) * SKB + aoff);
            // term 1: Ah x Bh
#pragma unroll
            for (int mi = 0; mi < 4; mi++)
#pragma unroll
                for (int ni = 0; ni < 8; ni++)
                    mma_bf16(acc[mi][ni], Ahf[mi], Bhf[ni][0], Bhf[ni][1]);
            // term 2: Al x Bh
#pragma unroll
            for (int mi = 0; mi < 4; mi++) {
                uint32_t Alf[4];
                LDSM_X4(Alf[0], Alf[1], Alf[2], Alf[3],
                        alB + (wm * 64 + mi * 16 + aRow) * SKB + aoff);
#pragma unroll
                for (int ni = 0; ni < 8; ni++)
                    mma_bf16(acc[mi][ni], Alf, Bhf[ni][0], Bhf[ni][1]);
            }
            // term 3: Ah x Bl
#pragma unroll
            for (int p = 0; p < 4; p++) {
                uint32_t r0, r1, r2, r3;
                LDSM_X4(r0, r1, r2, r3, blB + (wn * 64 + p * 16 + bN) * SKB + boff);
#pragma unroll
                for (int mi = 0; mi < 4; mi++) {
                    mma_bf16(acc[mi][2 * p],     Ahf[mi], r0, r1);
                    mma_bf16(acc[mi][2 * p + 1], Ahf[mi], r2, r3);
                }
            }
        }
        __syncthreads();
    }

    const int g  = lane >> 2;
    const int c2 = (lane & 3) * 2;

    if (EPI == 1) {
        // fp32 + bias (output projection); N=1024, n0 in [0,1024)
#pragma unroll
        for (int mi = 0; mi < 4; mi++) {
            const int row = m0 + wm * 64 + mi * 16 + g;
#pragma unroll
            for (int ni = 0; ni < 8; ni++) {
                const int col = n0 + wn * 64 + ni * 8 + c2;
                const float2 bb = *reinterpret_cast<const float2*>(b0p + col);
                float2 v0 = { acc[mi][ni][0] + bb.x, acc[mi][ni][1] + bb.y };
                float2 v1 = { acc[mi][ni][2] + bb.x, acc[mi][ni][3] + bb.y };
                *reinterpret_cast<float2*>(Cf + (size_t)row * Dz + col)       = v0;
                *reinterpret_cast<float2*>(Cf + (size_t)(row + 8) * Dz + col) = v1;
            }
        }
    } else {
        // QKV routed epilogue: whole CTA is inside one 1024-col segment
        const int seg = n0 >> 10;                  // 0,1,2
        const float* bias = (seg == 0) ? b0p : (seg == 1) ? b1p : b2p;
        const float scale = (seg == 0) ? 0.125f : 1.0f;
        uint32_t* oh = reinterpret_cast<uint32_t*>(seg == 0 ? QH : seg == 1 ? KH : VH);
        uint32_t* ol = reinterpret_cast<uint32_t*>(seg == 0 ? QL : seg == 1 ? KL : VL);
        const int nsegBase = n0 - (seg << 10);
#pragma unroll
        for (int mi = 0; mi < 4; mi++) {
            const int row0 = m0 + wm * 64 + mi * 16 + g;
#pragma unroll
            for (int ni = 0; ni < 8; ni++) {
                const int col = nsegBase + wn * 64 + ni * 8 + c2;   // even
                const float2 bb = *reinterpret_cast<const float2*>(bias + col);
                float v00 = (acc[mi][ni][0] + bb.x) * scale;
                float v01 = (acc[mi][ni][1] + bb.y) * scale;
                float v10 = (acc[mi][ni][2] + bb.x) * scale;
                float v11 = (acc[mi][ni][3] + bb.y) * scale;
                uint32_t h0, l0v, h1, l1v;
                splitpack(v00, v01, h0, l0v);
                splitpack(v10, v11, h1, l1v);
                const uint32_t i0 = ((uint32_t)row0 * Dz + col) >> 1;
                const uint32_t i1 = i0 + (8 * Dz >> 1);
                oh[i0] = h0; ol[i0] = l0v;
                oh[i1] = h1; ol[i1] = l1v;
            }
        }
    }
}

// =====================================================================
// HMMA flash attention (mainloop identical to R6 pass).
// Q read pre-split (hi/lo bf16, 1/8 folded); epilogue writes rep hi/lo.
// =====================================================================
constexpr int FSTR = 144;
constexpr int FTILE = 64 * FSTR;
constexpr int FBUF  = 4 * FTILE;
constexpr int FLASH_SMEM = 2 * FBUF;               // 73728

__global__ __launch_bounds__(256)
void flash_hmma(const __nv_bfloat16* __restrict__ Qhp, const __nv_bfloat16* __restrict__ Qlp,
                const __nv_bfloat16* __restrict__ Kh, const __nv_bfloat16* __restrict__ Kl,
                const __nv_bfloat16* __restrict__ Vh, const __nv_bfloat16* __restrict__ Vl,
                __nv_bfloat16* __restrict__ Rh, __nv_bfloat16* __restrict__ Rl)
{
    extern __shared__ char smem[];
    const uint32_t sbase = smem_u32(smem);
    const int tid = threadIdx.x, lane = tid & 31, wid = tid >> 5;
    const int g = lane >> 2, t4 = lane & 3;
    const int qt = blockIdx.x, h = blockIdx.y, b = blockIdx.z;
    const size_t base = (size_t)b * Pz * HD + (size_t)h * DKz;

    // ---- Q fragments direct from pre-split arrays (A-frag layout) ----
    uint32_t Qh[4][4], Ql[4][4];
    {
        const int row0 = qt * 128 + wid * 16 + g;
        const uint32_t* qh32 = reinterpret_cast<const uint32_t*>(Qhp) + ((base >> 1));
        const uint32_t* ql32 = reinterpret_cast<const uint32_t*>(Qlp) + ((base >> 1));
        const uint32_t r0 = (uint32_t)row0 * (HD >> 1);
        const uint32_t r1 = (uint32_t)(row0 + 8) * (HD >> 1);
#pragma unroll
        for (int s = 0; s < 4; s++) {
            const uint32_t cp0 = s * 8 + t4;       // u32 col index
            Qh[s][0] = qh32[r0 + cp0];     Ql[s][0] = ql32[r0 + cp0];
            Qh[s][1] = qh32[r1 + cp0];     Ql[s][1] = ql32[r1 + cp0];
            Qh[s][2] = qh32[r0 + cp0 + 4]; Ql[s][2] = ql32[r0 + cp0 + 4];
            Qh[s][3] = qh32[r1 + cp0 + 4]; Ql[s][3] = ql32[r1 + cp0 + 4];
        }
    }

    const __nv_bfloat16* srcs[4] = { Kh + base, Kl + base, Vh + base, Vl + base };

    auto issue = [&](int tt, int bf) {
#pragma unroll
        for (int p = 0; p < 4; p++) {
            const __nv_bfloat16* s = srcs[p] + (size_t)(tt * 64) * HD;
            const uint32_t dT = sbase + bf * FBUF + p * FTILE;
#pragma unroll
            for (int i = 0; i < 2; i++) {
                int lin = tid + i * 256;
                int row = lin >> 3, ch = lin & 7;
                CP_ASYNC16(dT + row * FSTR + ch * 16, s + (size_t)row * HD + ch * 8);
            }
        }
        CP_COMMIT();
    };

    const uint32_t bN = ((lane >> 4) & 1) * 8 + (lane & 7);
    const uint32_t bK = ((lane >> 3) & 1) * 8;
    const uint32_t part = lane >> 3;
    const uint32_t vRow = (part & 1) * 8 + (lane & 7);
    const uint32_t vCol = (part >> 1) * 8;

    float O[8][4];
#pragma unroll
    for (int nt = 0; nt < 8; nt++)
#pragma unroll
        for (int r = 0; r < 4; r++) O[nt][r] = 0.f;
    float m0 = -1e30f, m1 = -1e30f, l0 = 0.f, l1 = 0.f;

    issue(0, 0);
    const int nT = Pz / 64;
    for (int t = 0; t < nT; t++) {
        if (t + 1 < nT) { issue(t + 1, (t + 1) & 1); CP_WAIT1(); }
        else            { CP_WAIT0(); }
        __syncthreads();

        const uint32_t bb = sbase + (t & 1) * FBUF;
        const uint32_t khB = bb, klB = bb + FTILE;
        const uint32_t vhB = bb + 2 * FTILE, vlB = bb + 3 * FTILE;

        float Sa[8][4];
#pragma unroll
        for (int nt = 0; nt < 8; nt++)
#pragma unroll
            for (int r = 0; r < 4; r++) Sa[nt][r] = 0.f;

#pragma unroll
        for (int s = 0; s < 4; s++) {
            uint32_t B[8][2];
#pragma unroll
            for (int p = 0; p < 4; p++) {
                uint32_t r0, r1, r2, r3;
                LDSM_X4(r0, r1, r2, r3, khB + (p * 16 + bN) * FSTR + (bK + s * 16) * 2);
                B[2 * p][0] = r0; B[2 * p][1] = r1;
                B[2 * p + 1][0] = r2; B[2 * p + 1][1] = r3;
            }
#pragma unroll
            for (int nt = 0; nt < 8; nt++) mma_bf16(Sa[nt], Qh[s], B[nt][0], B[nt][1]);
#pragma unroll
            for (int nt = 0; nt < 8; nt++) mma_bf16(Sa[nt], Ql[s], B[nt][0], B[nt][1]);
#pragma unroll
            for (int p = 0; p < 4; p++) {
                uint32_t r0, r1, r2, r3;
                LDSM_X4(r0, r1, r2, r3, klB + (p * 16 + bN) * FSTR + (bK + s * 16) * 2);
                B[2 * p][0] = r0; B[2 * p][1] = r1;
                B[2 * p + 1][0] = r2; B[2 * p + 1][1] = r3;
            }
#pragma unroll
            for (int nt = 0; nt < 8; nt++) mma_bf16(Sa[nt], Qh[s], B[nt][0], B[nt][1]);
        }

        float ml0 = -1e30f, ml1 = -1e30f;
#pragma unroll
        for (int nt = 0; nt < 8; nt++) {
            ml0 = fmaxf(ml0, fmaxf(Sa[nt][0], Sa[nt][1]));
            ml1 = fmaxf(ml1, fmaxf(Sa[nt][2], Sa[nt][3]));
        }
        ml0 = fmaxf(ml0, __shfl_xor_sync(0xffffffffu, ml0, 1));
        ml0 = fmaxf(ml0, __shfl_xor_sync(0xffffffffu, ml0, 2));
        ml1 = fmaxf(ml1, __shfl_xor_sync(0xffffffffu, ml1, 1));
        ml1 = fmaxf(ml1, __shfl_xor_sync(0xffffffffu, ml1, 2));
        const float mn0 = fmaxf(m0, ml0), mn1 = fmaxf(m1, ml1);
        const float sc0 = fast_exp(m0 - mn0), sc1 = fast_exp(m1 - mn1);
        m0 = mn0; m1 = mn1;

        float ps0 = 0.f, ps1 = 0.f;
#pragma unroll
        for (int nt = 0; nt < 8; nt++) {
            Sa[nt][0] = fast_exp(Sa[nt][0] - mn0);
            Sa[nt][1] = fast_exp(Sa[nt][1] - mn0);
            Sa[nt][2] = fast_exp(Sa[nt][2] - mn1);
            Sa[nt][3] = fast_exp(Sa[nt][3] - mn1);
            ps0 += Sa[nt][0] + Sa[nt][1];
            ps1 += Sa[nt][2] + Sa[nt][3];
        }
        ps0 += __shfl_xor_sync(0xffffffffu, ps0, 1);
        ps0 += __shfl_xor_sync(0xffffffffu, ps0, 2);
        ps1 += __shfl_xor_sync(0xffffffffu, ps1, 1);
        ps1 += __shfl_xor_sync(0xffffffffu, ps1, 2);
        l0 = l0 * sc0 + ps0;
        l1 = l1 * sc1 + ps1;

#pragma unroll
        for (int nt = 0; nt < 8; nt++) {
            O[nt][0] *= sc0; O[nt][1] *= sc0;
            O[nt][2] *= sc1; O[nt][3] *= sc1;
        }

        uint32_t Ph[4][4], Pl[4][4];
#pragma unroll
        for (int s = 0; s < 4; s++) {
            splitpack(Sa[2 * s][0],     Sa[2 * s][1],     Ph[s][0], Pl[s][0]);
            splitpack(Sa[2 * s][2],     Sa[2 * s][3],     Ph[s][1], Pl[s][1]);
            splitpack(Sa[2 * s + 1][0], Sa[2 * s + 1][1], Ph[s][2], Pl[s][2]);
            splitpack(Sa[2 * s + 1][2], Sa[2 * s + 1][3], Ph[s][3], Pl[s][3]);
        }

#pragma unroll
        for (int s = 0; s < 4; s++) {
            uint32_t B[8][2];
#pragma unroll
            for (int p = 0; p < 4; p++) {
                uint32_t r0, r1, r2, r3;
                LDSM_X4_T(r0, r1, r2, r3,
                          vhB + (s * 16 + vRow) * FSTR + (p * 16 + vCol) * 2);
                B[2 * p][0] = r0; B[2 * p][1] = r1;
                B[2 * p + 1][0] = r2; B[2 * p + 1][1] = r3;
            }
#pragma unroll
            for (int nt = 0; nt < 8; nt++) mma_bf16(O[nt], Ph[s], B[nt][0], B[nt][1]);
#pragma unroll
            for (int nt = 0; nt < 8; nt++) mma_bf16(O[nt], Pl[s], B[nt][0], B[nt][1]);
#pragma unroll
            for (int p = 0; p < 4; p++) {
                uint32_t r0, r1, r2, r3;
                LDSM_X4_T(r0, r1, r2, r3,
                          vlB + (s * 16 + vRow) * FSTR + (p * 16 + vCol) * 2);
                B[2 * p][0] = r0; B[2 * p][1] = r1;
                B[2 * p + 1][0] = r2; B[2 * p + 1][1] = r3;
            }
#pragma unroll
            for (int nt = 0; nt < 8; nt++) mma_bf16(O[nt], Ph[s], B[nt][0], B[nt][1]);
        }
        __syncthreads();
    }

    // ---- finalize: write rep hi/lo bf16 (feeds output projection) ----
    const float inv0 = 1.f / l0, inv1 = 1.f / l1;
    const int row0 = qt * 128 + wid * 16 + g;
    uint32_t* rh32 = reinterpret_cast<uint32_t*>(Rh) + (base >> 1);
    uint32_t* rl32 = reinterpret_cast<uint32_t*>(Rl) + (base >> 1);
    const uint32_t r0 = (uint32_t)row0 * (HD >> 1);
    const uint32_t r1 = (uint32_t)(row0 + 8) * (HD >> 1);
    const int qc = 2 * t4;
#pragma unroll
    for (int nt = 0; nt < 8; nt++) {
        const uint32_t cp = (uint32_t)(nt * 8 + qc) >> 1;
        uint32_t h0, lo0, h1, lo1;
        splitpack(O[nt][0] * inv0, O[nt][1] * inv0, h0, lo0);
        splitpack(O[nt][2] * inv1, O[nt][3] * inv1, h1, lo1);
        rh32[r0 + cp] = h0; rl32[r0 + cp] = lo0;
        rh32[r1 + cp] = h1; rl32[r1 + cp] = lo1;
    }
}

// =====================================================================
// launcher
// =====================================================================
extern "C" void kernel_launch(void* const* d_in, const int* in_sizes, int n_in,
                              void* d_out, int out_size)
{
    const float* x  = (const float*)d_in[0];
    const float* Wq = (const float*)d_in[1];
    const float* bq = (const float*)d_in[2];
    const float* Wk = (const float*)d_in[3];
    const float* bk = (const float*)d_in[4];
    const float* Wv = (const float*)d_in[5];
    const float* bv = (const float*)d_in[6];
    const float* Wo = (const float*)d_in[7];
    const float* bo = (const float*)d_in[8];

    __nv_bfloat16 *xh, *xl, *wht, *wlt, *qh, *ql, *kh, *kl, *vh, *vl, *rh, *rl;
    cudaGetSymbolAddress((void**)&xh,  g_xh);
    cudaGetSymbolAddress((void**)&xl,  g_xl);
    cudaGetSymbolAddress((void**)&wht, g_wht);
    cudaGetSymbolAddress((void**)&wlt, g_wlt);
    cudaGetSymbolAddress((void**)&qh,  g_Qh);
    cudaGetSymbolAddress((void**)&ql,  g_Ql);
    cudaGetSymbolAddress((void**)&kh,  g_Kh);
    cudaGetSymbolAddress((void**)&kl,  g_Kl);
    cudaGetSymbolAddress((void**)&vh,  g_Vh);
    cudaGetSymbolAddress((void**)&vl,  g_Vl);
    cudaGetSymbolAddress((void**)&rh,  g_Rh);
    cudaGetSymbolAddress((void**)&rl,  g_Rl);

    cudaFuncSetAttribute(flash_hmma,
                         cudaFuncAttributeMaxDynamicSharedMemorySize, FLASH_SMEM);
    cudaFuncSetAttribute(gemm_wide<0>,
                         cudaFuncAttributeMaxDynamicSharedMemorySize, GEMM_SMEM);
    cudaFuncSetAttribute(gemm_wide<1>,
                         cudaFuncAttributeMaxDynamicSharedMemorySize, GEMM_SMEM);

    const int n4 = Mrows * Dz / 4;
    const dim3 wgrid(Dz / 32, Dz / 32);
    const dim3 wblk(32, 8);

    // input split + concatenated W^T split
    split_kernel<<<2048, 256>>>((const float4*)x, (__nv_bfloat162*)xh, (__nv_bfloat162*)xl, n4);
    wsplit_kernel<<<wgrid, wblk>>>(Wq, wht,                     wlt);
    wsplit_kernel<<<wgrid, wblk>>>(Wk, wht + (size_t)Dz * Dz,   wlt + (size_t)Dz * Dz);
    wsplit_kernel<<<wgrid, wblk>>>(Wv, wht + (size_t)2 * Dz * Dz, wlt + (size_t)2 * Dz * Dz);

    // fused QKV projection: N=3072, epilogue splits to bf16 hi/lo
    gemm_wide<0><<<dim3(3 * Dz / 256, Mrows / 128), 256, GEMM_SMEM>>>(
        xh, xl, wht, wlt, bq, bk, bv, nullptr,
        qh, ql, kh, kl, vh, vl);

    flash_hmma<<<dim3(Pz / 128, Hz, Bz), 256, FLASH_SMEM>>>(
        qh, ql, kh, kl, vh, vl, rh, rl);

    // output projection
    wsplit_kernel<<<wgrid, wblk>>>(Wo, wht, wlt);
    gemm_wide<1><<<dim3(Dz / 256, Mrows / 128), 256, GEMM_SMEM>>>(
        rh, rl, wht, wlt, bo, nullptr, nullptr, (float*)d_out,
        nullptr, nullptr, nullptr, nullptr, nullptr, nullptr);
}

// round 9
// speedup vs baseline: 3.0161x; 1.0256x over previous
#include <cuda_runtime.h>
#include <cuda_bf16.h>
#include <cstdint>
#include <math.h>

// Problem constants
constexpr int Bz  = 4;
constexpr int Pz  = 2048;
constexpr int Dz  = 1024;
constexpr int Hz  = 16;
constexpr int DKz = 64;
constexpr int Mrows = Bz * Pz;          // 8192
constexpr int HD   = Hz * DKz;          // 1024

// ---------------- scratch (allocation-free rule: __device__ globals) -------
__device__ __nv_bfloat16 g_xh [(size_t)Mrows * Dz];
__device__ __nv_bfloat16 g_xl [(size_t)Mrows * Dz];
__device__ __nv_bfloat16 g_wht[(size_t)3 * Dz * Dz];   // [3072,1024] or Wo in [0,1024)
__device__ __nv_bfloat16 g_wlt[(size_t)3 * Dz * Dz];
__device__ __nv_bfloat16 g_Qh [(size_t)Mrows * HD];
__device__ __nv_bfloat16 g_Ql [(size_t)Mrows * HD];
__device__ __nv_bfloat16 g_Kh [(size_t)Mrows * HD];
__device__ __nv_bfloat16 g_Kl [(size_t)Mrows * HD];
__device__ __nv_bfloat16 g_Vh [(size_t)Mrows * HD];
__device__ __nv_bfloat16 g_Vl [(size_t)Mrows * HD];
__device__ __nv_bfloat16 g_Rh [(size_t)Mrows * HD];
__device__ __nv_bfloat16 g_Rl [(size_t)Mrows * HD];

// =====================================================================
// baseline-PTX helpers (work on .target sm_103: no 'a' features!)
// =====================================================================
__device__ __forceinline__ uint32_t smem_u32(const void* p) {
    uint32_t a;
    asm("{ .reg .u64 t; cvta.to.shared.u64 t, %1; cvt.u32.u64 %0, t; }"
        : "=r"(a) : "l"(p));
    return a;
}
#define LDSM_X4(r0, r1, r2, r3, addr) \
    asm volatile("ldmatrix.sync.aligned.m8n8.x4.shared.b16 {%0,%1,%2,%3}, [%4];" \
                 : "=r"(r0), "=r"(r1), "=r"(r2), "=r"(r3) : "r"(addr))
#define LDSM_X4_T(r0, r1, r2, r3, addr) \
    asm volatile("ldmatrix.sync.aligned.m8n8.x4.trans.shared.b16 {%0,%1,%2,%3}, [%4];" \
                 : "=r"(r0), "=r"(r1), "=r"(r2), "=r"(r3) : "r"(addr))
#define CP_ASYNC16(dst, src) \
    asm volatile("cp.async.ca.shared.global [%0], [%1], 16;" :: "r"(dst), "l"(src))
#define CP_COMMIT() asm volatile("cp.async.commit_group;" ::: "memory")
#define CP_WAIT1()  asm volatile("cp.async.wait_group 1;" ::: "memory")
#define CP_WAIT0()  asm volatile("cp.async.wait_group 0;" ::: "memory")

__device__ __forceinline__ void mma_bf16(float* c, const uint32_t a[4],
                                         uint32_t b0, uint32_t b1) {
    asm volatile(
        "mma.sync.aligned.m16n8k16.row.col.f32.bf16.bf16.f32 "
        "{%0,%1,%2,%3}, {%4,%5,%6,%7}, {%8,%9}, {%0,%1,%2,%3};"
        : "+f"(c[0]), "+f"(c[1]), "+f"(c[2]), "+f"(c[3])
        : "r"(a[0]), "r"(a[1]), "r"(a[2]), "r"(a[3]), "r"(b0), "r"(b1));
}

// fast exp on FMA pipe (avoids the chip-wide MUFU floor)
__device__ __forceinline__ float fast_exp(float x) {
    float t = fmaxf(x * 1.4426950408889634f, -126.0f);
    float r = t + 12582912.0f;
    float i = r - 12582912.0f;
    float f = t - i;
    float p = 1.3333558e-3f;
    p = fmaf(p, f, 9.6181291e-3f);
    p = fmaf(p, f, 5.5504109e-2f);
    p = fmaf(p, f, 2.4022651e-1f);
    p = fmaf(p, f, 6.9314718e-1f);
    p = fmaf(p, f, 1.0f);
    float s = __int_as_float(((int)i + 127) << 23);
    return p * s;
}

__device__ __forceinline__ void split2(float x, __nv_bfloat16& h, __nv_bfloat16& l) {
    h = __float2bfloat16_rn(x);
    l = __float2bfloat16_rn(x - __bfloat162float(h));
}
__device__ __forceinline__ uint32_t pk2(__nv_bfloat16 a, __nv_bfloat16 b) {
    __nv_bfloat162 v; v.x = a; v.y = b;
    return reinterpret_cast<uint32_t&>(v);
}
__device__ __forceinline__ void splitpack(float a, float b, uint32_t& hi, uint32_t& lo) {
    __nv_bfloat16 ah, al, bh, bl;
    split2(a, ah, al); split2(b, bh, bl);
    hi = pk2(ah, bh); lo = pk2(al, bl);
}

// =====================================================================
// input split kernels
// =====================================================================
__global__ void split_kernel(const float4* __restrict__ src,
                             __nv_bfloat162* __restrict__ hi,
                             __nv_bfloat162* __restrict__ lo, int n4)
{
    int i = blockIdx.x * blockDim.x + threadIdx.x;
    int stride = gridDim.x * blockDim.x;
    for (; i < n4; i += stride) {
        float4 v = src[i];
        __nv_bfloat16 h0, h1, h2, h3, l0, l1, l2, l3;
        split2(v.x, h0, l0); split2(v.y, h1, l1);
        split2(v.z, h2, l2); split2(v.w, h3, l3);
        hi[2 * i]     = __halves2bfloat162(h0, h1);
        hi[2 * i + 1] = __halves2bfloat162(h2, h3);
        lo[2 * i]     = __halves2bfloat162(l0, l1);
        lo[2 * i + 1] = __halves2bfloat162(l2, l3);
    }
}

__global__ void wsplit_kernel(const float* __restrict__ W,
                              __nv_bfloat16* __restrict__ WhT,
                              __nv_bfloat16* __restrict__ WlT)
{
    __shared__ float s[32][33];
    const int n0 = blockIdx.x * 32, k0 = blockIdx.y * 32;
    const int tx = threadIdx.x, ty = threadIdx.y;   // (32, 8)
#pragma unroll
    for (int i = 0; i < 4; i++)
        s[ty + i * 8][tx] = W[(size_t)(k0 + ty + i * 8) * Dz + n0 + tx];
    __syncthreads();
#pragma unroll
    for (int i = 0; i < 4; i++) {
        const int n = n0 + ty + i * 8;
        const int k = k0 + tx;
        __nv_bfloat16 h, l;
        split2(s[tx][ty + i * 8], h, l);
        WhT[(size_t)n * Dz + k] = h;
        WlT[(size_t)n * Dz + k] = l;
    }
}

// =====================================================================
// HMMA split-bf16 GEMM, CTA 128x128, 8 warps of 64x32 (proven R4/R6
// shape: acc=64 regs, no spills), BK=32, cp.async double buffer.
// EPI=0: QKV fused epilogue -> bf16 hi/lo per 1024-col segment (Q x 1/8)
// EPI=1: fp32 out + bias (output projection)
// =====================================================================
constexpr int SKB   = 80;
constexpr int TILEB = 128 * SKB;           // 10240
constexpr int BUFB  = 4 * TILEB;           // 40960
constexpr int GEMM_SMEM = 2 * BUFB;        // 81920

template<int EPI>
__global__ __launch_bounds__(256)
void gemm_hmma3(const __nv_bfloat16* __restrict__ Ah, const __nv_bfloat16* __restrict__ Al,
                const __nv_bfloat16* __restrict__ Bh, const __nv_bfloat16* __restrict__ Bl,
                const float* __restrict__ b0p, const float* __restrict__ b1p,
                const float* __restrict__ b2p,
                float* __restrict__ Cf,
                __nv_bfloat16* __restrict__ QH, __nv_bfloat16* __restrict__ QL,
                __nv_bfloat16* __restrict__ KH, __nv_bfloat16* __restrict__ KL,
                __nv_bfloat16* __restrict__ VH, __nv_bfloat16* __restrict__ VL)
{
    extern __shared__ char smem[];
    const uint32_t sbase = smem_u32(smem);
    const int tid  = threadIdx.x;
    const int lane = tid & 31;
    const int wid  = tid >> 5;
    const int wm   = wid >> 2;       // 0..1  (64 rows each)
    const int wn   = wid & 3;        // 0..3  (32 cols each)
    const int m0 = blockIdx.y * 128;
    const int n0 = blockIdx.x * 128;

    const __nv_bfloat16* srcs[4] = {
        Ah + (size_t)m0 * Dz, Al + (size_t)m0 * Dz,
        Bh + (size_t)n0 * Dz, Bl + (size_t)n0 * Dz };

    float acc[4][4][4];
#pragma unroll
    for (int mi = 0; mi < 4; mi++)
#pragma unroll
        for (int ni = 0; ni < 4; ni++)
#pragma unroll
            for (int r = 0; r < 4; r++) acc[mi][ni][r] = 0.f;

    auto issue = [&](int t, int b) {
#pragma unroll
        for (int p = 0; p < 4; p++) {
            const __nv_bfloat16* s = srcs[p] + t * 32;
            const uint32_t dT = sbase + b * BUFB + p * TILEB;
#pragma unroll
            for (int i = 0; i < 2; i++) {
                int lin = tid + i * 256;           // 0..511
                int row = lin >> 2, kg = lin & 3;
                CP_ASYNC16(dT + row * SKB + kg * 16, s + (size_t)row * Dz + kg * 8);
            }
        }
        CP_COMMIT();
    };

    const uint32_t aRow = lane & 15;
    const uint32_t aK   = (lane >> 4) * 8;
    const uint32_t bN   = ((lane >> 4) & 1) * 8 + (lane & 7);
    const uint32_t bK   = ((lane >> 3) & 1) * 8;

    issue(0, 0);
    const int nk = Dz / 32;                        // 32
    for (int t = 0; t < nk; t++) {
        if (t + 1 < nk) { issue(t + 1, (t + 1) & 1); CP_WAIT1(); }
        else            { CP_WAIT0(); }
        __syncthreads();

        const uint32_t bb  = sbase + (t & 1) * BUFB;
        const uint32_t ahB = bb, alB = bb + TILEB;
        const uint32_t bhB = bb + 2 * TILEB, blB = bb + 3 * TILEB;

#pragma unroll
        for (int ks = 0; ks < 32; ks += 16) {
            const uint32_t aoff = (aK + ks) * 2;
            const uint32_t boff = (bK + ks) * 2;

            uint32_t Ahf[4][4], Bhf[4][2];
#pragma unroll
            for (int p = 0; p < 2; p++) {
                uint32_t r0, r1, r2, r3;
                LDSM_X4(r0, r1, r2, r3, bhB + (wn * 32 + p * 16 + bN) * SKB + boff);
                Bhf[2 * p][0] = r0; Bhf[2 * p][1] = r1;
                Bhf[2 * p + 1][0] = r2; Bhf[2 * p + 1][1] = r3;
            }
#pragma unroll
            for (int mi = 0; mi < 4; mi++)
                LDSM_X4(Ahf[mi][0], Ahf[mi][1], Ahf[mi][2], Ahf[mi][3],
                        ahB + (wm * 64 + mi * 16 + aRow) * SKB + aoff);
            // term 1: Ah x Bh
#pragma unroll
            for (int mi = 0; mi < 4; mi++)
#pragma unroll
                for (int ni = 0; ni < 4; ni++)
                    mma_bf16(acc[mi][ni], Ahf[mi], Bhf[ni][0], Bhf[ni][1]);
            // term 2: Al x Bh
#pragma unroll
            for (int mi = 0; mi < 4; mi++) {
                uint32_t Alf[4];
                LDSM_X4(Alf[0], Alf[1], Alf[2], Alf[3],
                        alB + (wm * 64 + mi * 16 + aRow) * SKB + aoff);
#pragma unroll
                for (int ni = 0; ni < 4; ni++)
                    mma_bf16(acc[mi][ni], Alf, Bhf[ni][0], Bhf[ni][1]);
            }
            // term 3: Ah x Bl
#pragma unroll
            for (int p = 0; p < 2; p++) {
                uint32_t r0, r1, r2, r3;
                LDSM_X4(r0, r1, r2, r3, blB + (wn * 32 + p * 16 + bN) * SKB + boff);
#pragma unroll
                for (int mi = 0; mi < 4; mi++) {
                    mma_bf16(acc[mi][2 * p],     Ahf[mi], r0, r1);
                    mma_bf16(acc[mi][2 * p + 1], Ahf[mi], r2, r3);
                }
            }
        }
        __syncthreads();
    }

    const int g  = lane >> 2;
    const int c2 = (lane & 3) * 2;

    if (EPI == 1) {
        // fp32 + bias (output projection); N=1024
#pragma unroll
        for (int mi = 0; mi < 4; mi++) {
            const int row = m0 + wm * 64 + mi * 16 + g;
#pragma unroll
            for (int ni = 0; ni < 4; ni++) {
                const int col = n0 + wn * 32 + ni * 8 + c2;
                const float2 bb = *reinterpret_cast<const float2*>(b0p + col);
                float2 v0 = { acc[mi][ni][0] + bb.x, acc[mi][ni][1] + bb.y };
                float2 v1 = { acc[mi][ni][2] + bb.x, acc[mi][ni][3] + bb.y };
                *reinterpret_cast<float2*>(Cf + (size_t)row * Dz + col)       = v0;
                *reinterpret_cast<float2*>(Cf + (size_t)(row + 8) * Dz + col) = v1;
            }
        }
    } else {
        // QKV routed epilogue: CTA N-tile (128) lies inside one 1024-col segment
        const int seg = n0 >> 10;                  // 0,1,2
        const float* bias = (seg == 0) ? b0p : (seg == 1) ? b1p : b2p;
        const float scale = (seg == 0) ? 0.125f : 1.0f;
        uint32_t* oh = reinterpret_cast<uint32_t*>(seg == 0 ? QH : seg == 1 ? KH : VH);
        uint32_t* ol = reinterpret_cast<uint32_t*>(seg == 0 ? QL : seg == 1 ? KL : VL);
        const int nsegBase = n0 & 1023;
#pragma unroll
        for (int mi = 0; mi < 4; mi++) {
            const int row0 = m0 + wm * 64 + mi * 16 + g;
#pragma unroll
            for (int ni = 0; ni < 4; ni++) {
                const int col = nsegBase + wn * 32 + ni * 8 + c2;   // even
                const float2 bb = *reinterpret_cast<const float2*>(bias + col);
                float v00 = (acc[mi][ni][0] + bb.x) * scale;
                float v01 = (acc[mi][ni][1] + bb.y) * scale;
                float v10 = (acc[mi][ni][2] + bb.x) * scale;
                float v11 = (acc[mi][ni][3] + bb.y) * scale;
                uint32_t h0, l0v, h1, l1v;
                splitpack(v00, v01, h0, l0v);
                splitpack(v10, v11, h1, l1v);
                const uint32_t i0 = ((uint32_t)row0 * Dz + col) >> 1;
                const uint32_t i1 = i0 + (8 * Dz >> 1);
                oh[i0] = h0; ol[i0] = l0v;
                oh[i1] = h1; ol[i1] = l1v;
            }
        }
    }
}

// =====================================================================
// HMMA flash attention (mainloop identical to R6/R8 pass).
// Q read pre-split (hi/lo bf16, 1/8 folded); epilogue writes rep hi/lo.
// =====================================================================
constexpr int FSTR = 144;
constexpr int FTILE = 64 * FSTR;
constexpr int FBUF  = 4 * FTILE;
constexpr int FLASH_SMEM = 2 * FBUF;               // 73728

__global__ __launch_bounds__(256)
void flash_hmma(const __nv_bfloat16* __restrict__ Qhp, const __nv_bfloat16* __restrict__ Qlp,
                const __nv_bfloat16* __restrict__ Kh, const __nv_bfloat16* __restrict__ Kl,
                const __nv_bfloat16* __restrict__ Vh, const __nv_bfloat16* __restrict__ Vl,
                __nv_bfloat16* __restrict__ Rh, __nv_bfloat16* __restrict__ Rl)
{
    extern __shared__ char smem[];
    const uint32_t sbase = smem_u32(smem);
    const int tid = threadIdx.x, lane = tid & 31, wid = tid >> 5;
    const int g = lane >> 2, t4 = lane & 3;
    const int qt = blockIdx.x, h = blockIdx.y, b = blockIdx.z;
    const size_t base = (size_t)b * Pz * HD + (size_t)h * DKz;

    // ---- Q fragments direct from pre-split arrays (A-frag layout) ----
    uint32_t Qh[4][4], Ql[4][4];
    {
        const int row0 = qt * 128 + wid * 16 + g;
        const uint32_t* qh32 = reinterpret_cast<const uint32_t*>(Qhp) + ((base >> 1));
        const uint32_t* ql32 = reinterpret_cast<const uint32_t*>(Qlp) + ((base >> 1));
        const uint32_t r0 = (uint32_t)row0 * (HD >> 1);
        const uint32_t r1 = (uint32_t)(row0 + 8) * (HD >> 1);
#pragma unroll
        for (int s = 0; s < 4; s++) {
            const uint32_t cp0 = s * 8 + t4;       // u32 col index
            Qh[s][0] = qh32[r0 + cp0];     Ql[s][0] = ql32[r0 + cp0];
            Qh[s][1] = qh32[r1 + cp0];     Ql[s][1] = ql32[r1 + cp0];
            Qh[s][2] = qh32[r0 + cp0 + 4]; Ql[s][2] = ql32[r0 + cp0 + 4];
            Qh[s][3] = qh32[r1 + cp0 + 4]; Ql[s][3] = ql32[r1 + cp0 + 4];
        }
    }

    const __nv_bfloat16* srcs[4] = { Kh + base, Kl + base, Vh + base, Vl + base };

    auto issue = [&](int tt, int bf) {
#pragma unroll
        for (int p = 0; p < 4; p++) {
            const __nv_bfloat16* s = srcs[p] + (size_t)(tt * 64) * HD;
            const uint32_t dT = sbase + bf * FBUF + p * FTILE;
#pragma unroll
            for (int i = 0; i < 2; i++) {
                int lin = tid + i * 256;
                int row = lin >> 3, ch = lin & 7;
                CP_ASYNC16(dT + row * FSTR + ch * 16, s + (size_t)row * HD + ch * 8);
            }
        }
        CP_COMMIT();
    };

    const uint32_t bN = ((lane >> 4) & 1) * 8 + (lane & 7);
    const uint32_t bK = ((lane >> 3) & 1) * 8;
    const uint32_t part = lane >> 3;
    const uint32_t vRow = (part & 1) * 8 + (lane & 7);
    const uint32_t vCol = (part >> 1) * 8;

    float O[8][4];
#pragma unroll
    for (int nt = 0; nt < 8; nt++)
#pragma unroll
        for (int r = 0; r < 4; r++) O[nt][r] = 0.f;
    float m0 = -1e30f, m1 = -1e30f, l0 = 0.f, l1 = 0.f;

    issue(0, 0);
    const int nT = Pz / 64;
    for (int t = 0; t < nT; t++) {
        if (t + 1 < nT) { issue(t + 1, (t + 1) & 1); CP_WAIT1(); }
        else            { CP_WAIT0(); }
        __syncthreads();

        const uint32_t bb = sbase + (t & 1) * FBUF;
        const uint32_t khB = bb, klB = bb + FTILE;
        const uint32_t vhB = bb + 2 * FTILE, vlB = bb + 3 * FTILE;

        float Sa[8][4];
#pragma unroll
        for (int nt = 0; nt < 8; nt++)
#pragma unroll
            for (int r = 0; r < 4; r++) Sa[nt][r] = 0.f;

#pragma unroll
        for (int s = 0; s < 4; s++) {
            uint32_t B[8][2];
#pragma unroll
            for (int p = 0; p < 4; p++) {
                uint32_t r0, r1, r2, r3;
                LDSM_X4(r0, r1, r2, r3, khB + (p * 16 + bN) * FSTR + (bK + s * 16) * 2);
                B[2 * p][0] = r0; B[2 * p][1] = r1;
                B[2 * p + 1][0] = r2; B[2 * p + 1][1] = r3;
            }
#pragma unroll
            for (int nt = 0; nt < 8; nt++) mma_bf16(Sa[nt], Qh[s], B[nt][0], B[nt][1]);
#pragma unroll
            for (int nt = 0; nt < 8; nt++) mma_bf16(Sa[nt], Ql[s], B[nt][0], B[nt][1]);
#pragma unroll
            for (int p = 0; p < 4; p++) {
                uint32_t r0, r1, r2, r3;
                LDSM_X4(r0, r1, r2, r3, klB + (p * 16 + bN) * FSTR + (bK + s * 16) * 2);
                B[2 * p][0] = r0; B[2 * p][1] = r1;
                B[2 * p + 1][0] = r2; B[2 * p + 1][1] = r3;
            }
#pragma unroll
            for (int nt = 0; nt < 8; nt++) mma_bf16(Sa[nt], Qh[s], B[nt][0], B[nt][1]);
        }

        float ml0 = -1e30f, ml1 = -1e30f;
#pragma unroll
        for (int nt = 0; nt < 8; nt++) {
            ml0 = fmaxf(ml0, fmaxf(Sa[nt][0], Sa[nt][1]));
            ml1 = fmaxf(ml1, fmaxf(Sa[nt][2], Sa[nt][3]));
        }
        ml0 = fmaxf(ml0, __shfl_xor_sync(0xffffffffu, ml0, 1));
        ml0 = fmaxf(ml0, __shfl_xor_sync(0xffffffffu, ml0, 2));
        ml1 = fmaxf(ml1, __shfl_xor_sync(0xffffffffu, ml1, 1));
        ml1 = fmaxf(ml1, __shfl_xor_sync(0xffffffffu, ml1, 2));
        const float mn0 = fmaxf(m0, ml0), mn1 = fmaxf(m1, ml1);
        const float sc0 = fast_exp(m0 - mn0), sc1 = fast_exp(m1 - mn1);
        m0 = mn0; m1 = mn1;

        float ps0 = 0.f, ps1 = 0.f;
#pragma unroll
        for (int nt = 0; nt < 8; nt++) {
            Sa[nt][0] = fast_exp(Sa[nt][0] - mn0);
            Sa[nt][1] = fast_exp(Sa[nt][1] - mn0);
            Sa[nt][2] = fast_exp(Sa[nt][2] - mn1);
            Sa[nt][3] = fast_exp(Sa[nt][3] - mn1);
            ps0 += Sa[nt][0] + Sa[nt][1];
            ps1 += Sa[nt][2] + Sa[nt][3];
        }
        ps0 += __shfl_xor_sync(0xffffffffu, ps0, 1);
        ps0 += __shfl_xor_sync(0xffffffffu, ps0, 2);
        ps1 += __shfl_xor_sync(0xffffffffu, ps1, 1);
        ps1 += __shfl_xor_sync(0xffffffffu, ps1, 2);
        l0 = l0 * sc0 + ps0;
        l1 = l1 * sc1 + ps1;

#pragma unroll
        for (int nt = 0; nt < 8; nt++) {
            O[nt][0] *= sc0; O[nt][1] *= sc0;
            O[nt][2] *= sc1; O[nt][3] *= sc1;
        }

        uint32_t Ph[4][4], Pl[4][4];
#pragma unroll
        for (int s = 0; s < 4; s++) {
            splitpack(Sa[2 * s][0],     Sa[2 * s][1],     Ph[s][0], Pl[s][0]);
            splitpack(Sa[2 * s][2],     Sa[2 * s][3],     Ph[s][1], Pl[s][1]);
            splitpack(Sa[2 * s + 1][0], Sa[2 * s + 1][1], Ph[s][2], Pl[s][2]);
            splitpack(Sa[2 * s + 1][2], Sa[2 * s + 1][3], Ph[s][3], Pl[s][3]);
        }

#pragma unroll
        for (int s = 0; s < 4; s++) {
            uint32_t B[8][2];
#pragma unroll
            for (int p = 0; p < 4; p++) {
                uint32_t r0, r1, r2, r3;
                LDSM_X4_T(r0, r1, r2, r3,
                          vhB + (s * 16 + vRow) * FSTR + (p * 16 + vCol) * 2);
                B[2 * p][0] = r0; B[2 * p][1] = r1;
                B[2 * p + 1][0] = r2; B[2 * p + 1][1] = r3;
            }
#pragma unroll
            for (int nt = 0; nt < 8; nt++) mma_bf16(O[nt], Ph[s], B[nt][0], B[nt][1]);
#pragma unroll
            for (int nt = 0; nt < 8; nt++) mma_bf16(O[nt], Pl[s], B[nt][0], B[nt][1]);
#pragma unroll
            for (int p = 0; p < 4; p++) {
                uint32_t r0, r1, r2, r3;
                LDSM_X4_T(r0, r1, r2, r3,
                          vlB + (s * 16 + vRow) * FSTR + (p * 16 + vCol) * 2);
                B[2 * p][0] = r0; B[2 * p][1] = r1;
                B[2 * p + 1][0] = r2; B[2 * p + 1][1] = r3;
            }
#pragma unroll
            for (int nt = 0; nt < 8; nt++) mma_bf16(O[nt], Ph[s], B[nt][0], B[nt][1]);
        }
        __syncthreads();
    }

    // ---- finalize: write rep hi/lo bf16 (feeds output projection) ----
    const float inv0 = 1.f / l0, inv1 = 1.f / l1;
    const int row0 = qt * 128 + wid * 16 + g;
    uint32_t* rh32 = reinterpret_cast<uint32_t*>(Rh) + (base >> 1);
    uint32_t* rl32 = reinterpret_cast<uint32_t*>(Rl) + (base >> 1);
    const uint32_t r0 = (uint32_t)row0 * (HD >> 1);
    const uint32_t r1 = (uint32_t)(row0 + 8) * (HD >> 1);
    const int qc = 2 * t4;
#pragma unroll
    for (int nt = 0; nt < 8; nt++) {
        const uint32_t cp = (uint32_t)(nt * 8 + qc) >> 1;
        uint32_t h0, lo0, h1, lo1;
        splitpack(O[nt][0] * inv0, O[nt][1] * inv0, h0, lo0);
        splitpack(O[nt][2] * inv1, O[nt][3] * inv1, h1, lo1);
        rh32[r0 + cp] = h0; rl32[r0 + cp] = lo0;
        rh32[r1 + cp] = h1; rl32[r1 + cp] = lo1;
    }
}

// =====================================================================
// launcher
// =====================================================================
extern "C" void kernel_launch(void* const* d_in, const int* in_sizes, int n_in,
                              void* d_out, int out_size)
{
    const float* x  = (const float*)d_in[0];
    const float* Wq = (const float*)d_in[1];
    const float* bq = (const float*)d_in[2];
    const float* Wk = (const float*)d_in[3];
    const float* bk = (const float*)d_in[4];
    const float* Wv = (const float*)d_in[5];
    const float* bv = (const float*)d_in[6];
    const float* Wo = (const float*)d_in[7];
    const float* bo = (const float*)d_in[8];

    __nv_bfloat16 *xh, *xl, *wht, *wlt, *qh, *ql, *kh, *kl, *vh, *vl, *rh, *rl;
    cudaGetSymbolAddress((void**)&xh,  g_xh);
    cudaGetSymbolAddress((void**)&xl,  g_xl);
    cudaGetSymbolAddress((void**)&wht, g_wht);
    cudaGetSymbolAddress((void**)&wlt, g_wlt);
    cudaGetSymbolAddress((void**)&qh,  g_Qh);
    cudaGetSymbolAddress((void**)&ql,  g_Ql);
    cudaGetSymbolAddress((void**)&kh,  g_Kh);
    cudaGetSymbolAddress((void**)&kl,  g_Kl);
    cudaGetSymbolAddress((void**)&vh,  g_Vh);
    cudaGetSymbolAddress((void**)&vl,  g_Vl);
    cudaGetSymbolAddress((void**)&rh,  g_Rh);
    cudaGetSymbolAddress((void**)&rl,  g_Rl);

    cudaFuncSetAttribute(flash_hmma,
                         cudaFuncAttributeMaxDynamicSharedMemorySize, FLASH_SMEM);
    cudaFuncSetAttribute(gemm_hmma3<0>,
                         cudaFuncAttributeMaxDynamicSharedMemorySize, GEMM_SMEM);
    cudaFuncSetAttribute(gemm_hmma3<1>,
                         cudaFuncAttributeMaxDynamicSharedMemorySize, GEMM_SMEM);

    const int n4 = Mrows * Dz / 4;
    const dim3 wgrid(Dz / 32, Dz / 32);
    const dim3 wblk(32, 8);

    // input split + concatenated W^T split
    split_kernel<<<2048, 256>>>((const float4*)x, (__nv_bfloat162*)xh, (__nv_bfloat162*)xl, n4);
    wsplit_kernel<<<wgrid, wblk>>>(Wq, wht,                       wlt);
    wsplit_kernel<<<wgrid, wblk>>>(Wk, wht + (size_t)Dz * Dz,     wlt + (size_t)Dz * Dz);
    wsplit_kernel<<<wgrid, wblk>>>(Wv, wht + (size_t)2 * Dz * Dz, wlt + (size_t)2 * Dz * Dz);

    // fused QKV projection: N=3072, epilogue splits to bf16 hi/lo
    gemm_hmma3<0><<<dim3(3 * Dz / 128, Mrows / 128), 256, GEMM_SMEM>>>(
        xh, xl, wht, wlt, bq, bk, bv, nullptr,
        qh, ql, kh, kl, vh, vl);

    flash_hmma<<<dim3(Pz / 128, Hz, Bz), 256, FLASH_SMEM>>>(
        qh, ql, kh, kl, vh, vl, rh, rl);

    // output projection
    wsplit_kernel<<<wgrid, wblk>>>(Wo, wht, wlt);
    gemm_hmma3<1><<<dim3(Dz / 128, Mrows / 128), 256, GEMM_SMEM>>>(
        rh, rl, wht, wlt, bo, nullptr, nullptr, (float*)d_out,
        nullptr, nullptr, nullptr, nullptr, nullptr, nullptr);
}

// round 11
// speedup vs baseline: 3.0639x; 1.0158x over previous
#include <cuda_runtime.h>
#include <cuda_bf16.h>
#include <cstdint>
#include <math.h>

// Problem constants
constexpr int Bz  = 4;
constexpr int Pz  = 2048;
constexpr int Dz  = 1024;
constexpr int Hz  = 16;
constexpr int DKz = 64;
constexpr int Mrows = Bz * Pz;          // 8192
constexpr int HD   = Hz * DKz;          // 1024

// ---------------- scratch (allocation-free rule: __device__ globals) -------
__device__ __nv_bfloat16 g_xh [(size_t)Mrows * Dz];
__device__ __nv_bfloat16 g_xl [(size_t)Mrows * Dz];
__device__ __nv_bfloat16 g_wht[(size_t)3 * Dz * Dz];   // [3072,1024] or Wo in [0,1024)
__device__ __nv_bfloat16 g_wlt[(size_t)3 * Dz * Dz];
__device__ __nv_bfloat16 g_Qh [(size_t)Mrows * HD];
__device__ __nv_bfloat16 g_Ql [(size_t)Mrows * HD];
__device__ __nv_bfloat16 g_Kh [(size_t)Mrows * HD];
__device__ __nv_bfloat16 g_Kl [(size_t)Mrows * HD];
__device__ __nv_bfloat16 g_Vh [(size_t)Mrows * HD];
__device__ __nv_bfloat16 g_Vl [(size_t)Mrows * HD];
__device__ __nv_bfloat16 g_Rh [(size_t)Mrows * HD];
__device__ __nv_bfloat16 g_Rl [(size_t)Mrows * HD];

// =====================================================================
// baseline-PTX helpers (work on .target sm_103: no 'a' features!)
// =====================================================================
__device__ __forceinline__ uint32_t smem_u32(const void* p) {
    uint32_t a;
    asm("{ .reg .u64 t; cvta.to.shared.u64 t, %1; cvt.u32.u64 %0, t; }"
        : "=r"(a) : "l"(p));
    return a;
}
#define LDSM_X4(r0, r1, r2, r3, addr) \
    asm volatile("ldmatrix.sync.aligned.m8n8.x4.shared.b16 {%0,%1,%2,%3}, [%4];" \
                 : "=r"(r0), "=r"(r1), "=r"(r2), "=r"(r3) : "r"(addr))
#define LDSM_X4_T(r0, r1, r2, r3, addr) \
    asm volatile("ldmatrix.sync.aligned.m8n8.x4.trans.shared.b16 {%0,%1,%2,%3}, [%4];" \
                 : "=r"(r0), "=r"(r1), "=r"(r2), "=r"(r3) : "r"(addr))
#define CP_ASYNC16(dst, src) \
    asm volatile("cp.async.ca.shared.global [%0], [%1], 16;" :: "r"(dst), "l"(src))
#define CP_COMMIT() asm volatile("cp.async.commit_group;" ::: "memory")
#define CP_WAIT1()  asm volatile("cp.async.wait_group 1;" ::: "memory")
#define CP_WAIT0()  asm volatile("cp.async.wait_group 0;" ::: "memory")

__device__ __forceinline__ void mma_bf16(float* c, const uint32_t a[4],
                                         uint32_t b0, uint32_t b1) {
    asm volatile(
        "mma.sync.aligned.m16n8k16.row.col.f32.bf16.bf16.f32 "
        "{%0,%1,%2,%3}, {%4,%5,%6,%7}, {%8,%9}, {%0,%1,%2,%3};"
        : "+f"(c[0]), "+f"(c[1]), "+f"(c[2]), "+f"(c[3])
        : "r"(a[0]), "r"(a[1]), "r"(a[2]), "r"(a[3]), "r"(b0), "r"(b1));
}

// fast exp on FMA pipe (avoids the chip-wide MUFU floor)
__device__ __forceinline__ float fast_exp(float x) {
    float t = fmaxf(x * 1.4426950408889634f, -126.0f);
    float r = t + 12582912.0f;
    float i = r - 12582912.0f;
    float f = t - i;
    float p = 1.3333558e-3f;
    p = fmaf(p, f, 9.6181291e-3f);
    p = fmaf(p, f, 5.5504109e-2f);
    p = fmaf(p, f, 2.4022651e-1f);
    p = fmaf(p, f, 6.9314718e-1f);
    p = fmaf(p, f, 1.0f);
    float s = __int_as_float(((int)i + 127) << 23);
    return p * s;
}

__device__ __forceinline__ void split2(float x, __nv_bfloat16& h, __nv_bfloat16& l) {
    h = __float2bfloat16_rn(x);
    l = __float2bfloat16_rn(x - __bfloat162float(h));
}
__device__ __forceinline__ uint32_t pk2(__nv_bfloat16 a, __nv_bfloat16 b) {
    __nv_bfloat162 v; v.x = a; v.y = b;
    return reinterpret_cast<uint32_t&>(v);
}
__device__ __forceinline__ void splitpack(float a, float b, uint32_t& hi, uint32_t& lo) {
    __nv_bfloat16 ah, al, bh, bl;
    split2(a, ah, al); split2(b, bh, bl);
    hi = pk2(ah, bh); lo = pk2(al, bl);
}

// =====================================================================
// input split kernels
// =====================================================================
__global__ void split_kernel(const float4* __restrict__ src,
                             __nv_bfloat162* __restrict__ hi,
                             __nv_bfloat162* __restrict__ lo, int n4)
{
    int i = blockIdx.x * blockDim.x + threadIdx.x;
    int stride = gridDim.x * blockDim.x;
    for (; i < n4; i += stride) {
        float4 v = src[i];
        __nv_bfloat16 h0, h1, h2, h3, l0, l1, l2, l3;
        split2(v.x, h0, l0); split2(v.y, h1, l1);
        split2(v.z, h2, l2); split2(v.w, h3, l3);
        hi[2 * i]     = __halves2bfloat162(h0, h1);
        hi[2 * i + 1] = __halves2bfloat162(h2, h3);
        lo[2 * i]     = __halves2bfloat162(l0, l1);
        lo[2 * i + 1] = __halves2bfloat162(l2, l3);
    }
}

__global__ void wsplit_kernel(const float* __restrict__ W,
                              __nv_bfloat16* __restrict__ WhT,
                              __nv_bfloat16* __restrict__ WlT)
{
    __shared__ float s[32][33];
    const int n0 = blockIdx.x * 32, k0 = blockIdx.y * 32;
    const int tx = threadIdx.x, ty = threadIdx.y;   // (32, 8)
#pragma unroll
    for (int i = 0; i < 4; i++)
        s[ty + i * 8][tx] = W[(size_t)(k0 + ty + i * 8) * Dz + n0 + tx];
    __syncthreads();
#pragma unroll
    for (int i = 0; i < 4; i++) {
        const int n = n0 + ty + i * 8;
        const int k = k0 + tx;
        __nv_bfloat16 h, l;
        split2(s[tx][ty + i * 8], h, l);
        WhT[(size_t)n * Dz + k] = h;
        WlT[(size_t)n * Dz + k] = l;
    }
}

// =====================================================================
// HMMA split-bf16 GEMM, CTA 128x128, 8 warps of 64x32, BK=32.
// __launch_bounds__(256, 2): cap regs at 128 -> 2 CTAs/SM (smem
// 2x81920=160KB fits) -> 4 warps/SMSP to fill issue slots across
// syncthreads/cp.async/LDSM stalls.
// EPI=0: QKV fused epilogue -> bf16 hi/lo per 1024-col segment (Q x 1/8)
// EPI=1: fp32 out + bias (output projection)
// =====================================================================
constexpr int SKB   = 80;
constexpr int TILEB = 128 * SKB;           // 10240
constexpr int BUFB  = 4 * TILEB;           // 40960
constexpr int GEMM_SMEM = 2 * BUFB;        // 81920

template<int EPI>
__global__ __launch_bounds__(256, 2)
void gemm_hmma3(const __nv_bfloat16* __restrict__ Ah, const __nv_bfloat16* __restrict__ Al,
                const __nv_bfloat16* __restrict__ Bh, const __nv_bfloat16* __restrict__ Bl,
                const float* __restrict__ b0p, const float* __restrict__ b1p,
                const float* __restrict__ b2p,
                float* __restrict__ Cf,
                __nv_bfloat16* __restrict__ QH, __nv_bfloat16* __restrict__ QL,
                __nv_bfloat16* __restrict__ KH, __nv_bfloat16* __restrict__ KL,
                __nv_bfloat16* __restrict__ VH, __nv_bfloat16* __restrict__ VL)
{
    extern __shared__ char smem[];
    const uint32_t sbase = smem_u32(smem);
    const int tid  = threadIdx.x;
    const int lane = tid & 31;
    const int wid  = tid >> 5;
    const int wm   = wid >> 2;       // 0..1  (64 rows each)
    const int wn   = wid & 3;        // 0..3  (32 cols each)
    const int m0 = blockIdx.y * 128;
    const int n0 = blockIdx.x * 128;

    const __nv_bfloat16* srcs[4] = {
        Ah + (size_t)m0 * Dz, Al + (size_t)m0 * Dz,
        Bh + (size_t)n0 * Dz, Bl + (size_t)n0 * Dz };

    float acc[4][4][4];
#pragma unroll
    for (int mi = 0; mi < 4; mi++)
#pragma unroll
        for (int ni = 0; ni < 4; ni++)
#pragma unroll
            for (int r = 0; r < 4; r++) acc[mi][ni][r] = 0.f;

    auto issue = [&](int t, int b) {
#pragma unroll
        for (int p = 0; p < 4; p++) {
            const __nv_bfloat16* s = srcs[p] + t * 32;
            const uint32_t dT = sbase + b * BUFB + p * TILEB;
#pragma unroll
            for (int i = 0; i < 2; i++) {
                int lin = tid + i * 256;           // 0..511
                int row = lin >> 2, kg = lin & 3;
                CP_ASYNC16(dT + row * SKB + kg * 16, s + (size_t)row * Dz + kg * 8);
            }
        }
        CP_COMMIT();
    };

    const uint32_t aRow = lane & 15;
    const uint32_t aK   = (lane >> 4) * 8;
    const uint32_t bN   = ((lane >> 4) & 1) * 8 + (lane & 7);
    const uint32_t bK   = ((lane >> 3) & 1) * 8;

    issue(0, 0);
    const int nk = Dz / 32;                        // 32
    for (int t = 0; t < nk; t++) {
        if (t + 1 < nk) { issue(t + 1, (t + 1) & 1); CP_WAIT1(); }
        else            { CP_WAIT0(); }
        __syncthreads();

        const uint32_t bb  = sbase + (t & 1) * BUFB;
        const uint32_t ahB = bb, alB = bb + TILEB;
        const uint32_t bhB = bb + 2 * TILEB, blB = bb + 3 * TILEB;

#pragma unroll
        for (int ks = 0; ks < 32; ks += 16) {
            const uint32_t aoff = (aK + ks) * 2;
            const uint32_t boff = (bK + ks) * 2;

            uint32_t Ahf[4][4], Bhf[4][2];
#pragma unroll
            for (int p = 0; p < 2; p++) {
                uint32_t r0, r1, r2, r3;
                LDSM_X4(r0, r1, r2, r3, bhB + (wn * 32 + p * 16 + bN) * SKB + boff);
                Bhf[2 * p][0] = r0; Bhf[2 * p][1] = r1;
                Bhf[2 * p + 1][0] = r2; Bhf[2 * p + 1][1] = r3;
            }
#pragma unroll
            for (int mi = 0; mi < 4; mi++)
                LDSM_X4(Ahf[mi][0], Ahf[mi][1], Ahf[mi][2], Ahf[mi][3],
                        ahB + (wm * 64 + mi * 16 + aRow) * SKB + aoff);
            // term 1: Ah x Bh
#pragma unroll
            for (int mi = 0; mi < 4; mi++)
#pragma unroll
                for (int ni = 0; ni < 4; ni++)
                    mma_bf16(acc[mi][ni], Ahf[mi], Bhf[ni][0], Bhf[ni][1]);
            // term 2: Al x Bh
#pragma unroll
            for (int mi = 0; mi < 4; mi++) {
                uint32_t Alf[4];
                LDSM_X4(Alf[0], Alf[1], Alf[2], Alf[3],
                        alB + (wm * 64 + mi * 16 + aRow) * SKB + aoff);
#pragma unroll
                for (int ni = 0; ni < 4; ni++)
                    mma_bf16(acc[mi][ni], Alf, Bhf[ni][0], Bhf[ni][1]);
            }
            // term 3: Ah x Bl
#pragma unroll
            for (int p = 0; p < 2; p++) {
                uint32_t r0, r1, r2, r3;
                LDSM_X4(r0, r1, r2, r3, blB + (wn * 32 + p * 16 + bN) * SKB + boff);
#pragma unroll
                for (int mi = 0; mi < 4; mi++) {
                    mma_bf16(acc[mi][2 * p],     Ahf[mi], r0, r1);
                    mma_bf16(acc[mi][2 * p + 1], Ahf[mi], r2, r3);
                }
            }
        }
        __syncthreads();
    }

    const int g  = lane >> 2;
    const int c2 = (lane & 3) * 2;

    if (EPI == 1) {
        // fp32 + bias (output projection); N=1024
#pragma unroll
        for (int mi = 0; mi < 4; mi++) {
            const int row = m0 + wm * 64 + mi * 16 + g;
#pragma unroll
            for (int ni = 0; ni < 4; ni++) {
                const int col = n0 + wn * 32 + ni * 8 + c2;
                const float2 bb = *reinterpret_cast<const float2*>(b0p + col);
                float2 v0 = { acc[mi][ni][0] + bb.x, acc[mi][ni][1] + bb.y };
                float2 v1 = { acc[mi][ni][2] + bb.x, acc[mi][ni][3] + bb.y };
                *reinterpret_cast<float2*>(Cf + (size_t)row * Dz + col)       = v0;
                *reinterpret_cast<float2*>(Cf + (size_t)(row + 8) * Dz + col) = v1;
            }
        }
    } else {
        // QKV routed epilogue: CTA N-tile (128) lies inside one 1024-col segment
        const int seg = n0 >> 10;                  // 0,1,2
        const float* bias = (seg == 0) ? b0p : (seg == 1) ? b1p : b2p;
        const float scale = (seg == 0) ? 0.125f : 1.0f;
        uint32_t* oh = reinterpret_cast<uint32_t*>(seg == 0 ? QH : seg == 1 ? KH : VH);
        uint32_t* ol = reinterpret_cast<uint32_t*>(seg == 0 ? QL : seg == 1 ? KL : VL);
        const int nsegBase = n0 & 1023;
#pragma unroll
        for (int mi = 0; mi < 4; mi++) {
            const int row0 = m0 + wm * 64 + mi * 16 + g;
#pragma unroll
            for (int ni = 0; ni < 4; ni++) {
                const int col = nsegBase + wn * 32 + ni * 8 + c2;   // even
                const float2 bb = *reinterpret_cast<const float2*>(bias + col);
                float v00 = (acc[mi][ni][0] + bb.x) * scale;
                float v01 = (acc[mi][ni][1] + bb.y) * scale;
                float v10 = (acc[mi][ni][2] + bb.x) * scale;
                float v11 = (acc[mi][ni][3] + bb.y) * scale;
                uint32_t h0, l0v, h1, l1v;
                splitpack(v00, v01, h0, l0v);
                splitpack(v10, v11, h1, l1v);
                const uint32_t i0 = ((uint32_t)row0 * Dz + col) >> 1;
                const uint32_t i1 = i0 + (8 * Dz >> 1);
                oh[i0] = h0; ol[i0] = l0v;
                oh[i1] = h1; ol[i1] = l1v;
            }
        }
    }
}

// =====================================================================
// HMMA flash attention (mainloop identical to R6/R8/R9 pass).
// Q read pre-split (hi/lo bf16, 1/8 folded); epilogue writes rep hi/lo.
// =====================================================================
constexpr int FSTR = 144;
constexpr int FTILE = 64 * FSTR;
constexpr int FBUF  = 4 * FTILE;
constexpr int FLASH_SMEM = 2 * FBUF;               // 73728

__global__ __launch_bounds__(256)
void flash_hmma(const __nv_bfloat16* __restrict__ Qhp, const __nv_bfloat16* __restrict__ Qlp,
                const __nv_bfloat16* __restrict__ Kh, const __nv_bfloat16* __restrict__ Kl,
                const __nv_bfloat16* __restrict__ Vh, const __nv_bfloat16* __restrict__ Vl,
                __nv_bfloat16* __restrict__ Rh, __nv_bfloat16* __restrict__ Rl)
{
    extern __shared__ char smem[];
    const uint32_t sbase = smem_u32(smem);
    const int tid = threadIdx.x, lane = tid & 31, wid = tid >> 5;
    const int g = lane >> 2, t4 = lane & 3;
    const int qt = blockIdx.x, h = blockIdx.y, b = blockIdx.z;
    const size_t base = (size_t)b * Pz * HD + (size_t)h * DKz;

    // ---- Q fragments direct from pre-split arrays (A-frag layout) ----
    uint32_t Qh[4][4], Ql[4][4];
    {
        const int row0 = qt * 128 + wid * 16 + g;
        const uint32_t* qh32 = reinterpret_cast<const uint32_t*>(Qhp) + ((base >> 1));
        const uint32_t* ql32 = reinterpret_cast<const uint32_t*>(Qlp) + ((base >> 1));
        const uint32_t r0 = (uint32_t)row0 * (HD >> 1);
        const uint32_t r1 = (uint32_t)(row0 + 8) * (HD >> 1);
#pragma unroll
        for (int s = 0; s < 4; s++) {
            const uint32_t cp0 = s * 8 + t4;       // u32 col index
            Qh[s][0] = qh32[r0 + cp0];     Ql[s][0] = ql32[r0 + cp0];
            Qh[s][1] = qh32[r1 + cp0];     Ql[s][1] = ql32[r1 + cp0];
            Qh[s][2] = qh32[r0 + cp0 + 4]; Ql[s][2] = ql32[r0 + cp0 + 4];
            Qh[s][3] = qh32[r1 + cp0 + 4]; Ql[s][3] = ql32[r1 + cp0 + 4];
        }
    }

    const __nv_bfloat16* srcs[4] = { Kh + base, Kl + base, Vh + base, Vl + base };

    auto issue = [&](int tt, int bf) {
#pragma unroll
        for (int p = 0; p < 4; p++) {
            const __nv_bfloat16* s = srcs[p] + (size_t)(tt * 64) * HD;
            const uint32_t dT = sbase + bf * FBUF + p * FTILE;
#pragma unroll
            for (int i = 0; i < 2; i++) {
                int lin = tid + i * 256;
                int row = lin >> 3, ch = lin & 7;
                CP_ASYNC16(dT + row * FSTR + ch * 16, s + (size_t)row * HD + ch * 8);
            }
        }
        CP_COMMIT();
    };

    const uint32_t bN = ((lane >> 4) & 1) * 8 + (lane & 7);
    const uint32_t bK = ((lane >> 3) & 1) * 8;
    const uint32_t part = lane >> 3;
    const uint32_t vRow = (part & 1) * 8 + (lane & 7);
    const uint32_t vCol = (part >> 1) * 8;

    float O[8][4];
#pragma unroll
    for (int nt = 0; nt < 8; nt++)
#pragma unroll
        for (int r = 0; r < 4; r++) O[nt][r] = 0.f;
    float m0 = -1e30f, m1 = -1e30f, l0 = 0.f, l1 = 0.f;

    issue(0, 0);
    const int nT = Pz / 64;
    for (int t = 0; t < nT; t++) {
        if (t + 1 < nT) { issue(t + 1, (t + 1) & 1); CP_WAIT1(); }
        else            { CP_WAIT0(); }
        __syncthreads();

        const uint32_t bb = sbase + (t & 1) * FBUF;
        const uint32_t khB = bb, klB = bb + FTILE;
        const uint32_t vhB = bb + 2 * FTILE, vlB = bb + 3 * FTILE;

        float Sa[8][4];
#pragma unroll
        for (int nt = 0; nt < 8; nt++)
#pragma unroll
            for (int r = 0; r < 4; r++) Sa[nt][r] = 0.f;

#pragma unroll
        for (int s = 0; s < 4; s++) {
            uint32_t B[8][2];
#pragma unroll
            for (int p = 0; p < 4; p++) {
                uint32_t r0, r1, r2, r3;
                LDSM_X4(r0, r1, r2, r3, khB + (p * 16 + bN) * FSTR + (bK + s * 16) * 2);
                B[2 * p][0] = r0; B[2 * p][1] = r1;
                B[2 * p + 1][0] = r2; B[2 * p + 1][1] = r3;
            }
#pragma unroll
            for (int nt = 0; nt < 8; nt++) mma_bf16(Sa[nt], Qh[s], B[nt][0], B[nt][1]);
#pragma unroll
            for (int nt = 0; nt < 8; nt++) mma_bf16(Sa[nt], Ql[s], B[nt][0], B[nt][1]);
#pragma unroll
            for (int p = 0; p < 4; p++) {
                uint32_t r0, r1, r2, r3;
                LDSM_X4(r0, r1, r2, r3, klB + (p * 16 + bN) * FSTR + (bK + s * 16) * 2);
                B[2 * p][0] = r0; B[2 * p][1] = r1;
                B[2 * p + 1][0] = r2; B[2 * p + 1][1] = r3;
            }
#pragma unroll
            for (int nt = 0; nt < 8; nt++) mma_bf16(Sa[nt], Qh[s], B[nt][0], B[nt][1]);
        }

        float ml0 = -1e30f, ml1 = -1e30f;
#pragma unroll
        for (int nt = 0; nt < 8; nt++) {
            ml0 = fmaxf(ml0, fmaxf(Sa[nt][0], Sa[nt][1]));
            ml1 = fmaxf(ml1, fmaxf(Sa[nt][2], Sa[nt][3]));
        }
        ml0 = fmaxf(ml0, __shfl_xor_sync(0xffffffffu, ml0, 1));
        ml0 = fmaxf(ml0, __shfl_xor_sync(0xffffffffu, ml0, 2));
        ml1 = fmaxf(ml1, __shfl_xor_sync(0xffffffffu, ml1, 1));
        ml1 = fmaxf(ml1, __shfl_xor_sync(0xffffffffu, ml1, 2));
        const float mn0 = fmaxf(m0, ml0), mn1 = fmaxf(m1, ml1);
        const float sc0 = fast_exp(m0 - mn0), sc1 = fast_exp(m1 - mn1);
        m0 = mn0; m1 = mn1;

        float ps0 = 0.f, ps1 = 0.f;
#pragma unroll
        for (int nt = 0; nt < 8; nt++) {
            Sa[nt][0] = fast_exp(Sa[nt][0] - mn0);
            Sa[nt][1] = fast_exp(Sa[nt][1] - mn0);
            Sa[nt][2] = fast_exp(Sa[nt][2] - mn1);
            Sa[nt][3] = fast_exp(Sa[nt][3] - mn1);
            ps0 += Sa[nt][0] + Sa[nt][1];
            ps1 += Sa[nt][2] + Sa[nt][3];
        }
        ps0 += __shfl_xor_sync(0xffffffffu, ps0, 1);
        ps0 += __shfl_xor_sync(0xffffffffu, ps0, 2);
        ps1 += __shfl_xor_sync(0xffffffffu, ps1, 1);
        ps1 += __shfl_xor_sync(0xffffffffu, ps1, 2);
        l0 = l0 * sc0 + ps0;
        l1 = l1 * sc1 + ps1;

#pragma unroll
        for (int nt = 0; nt < 8; nt++) {
            O[nt][0] *= sc0; O[nt][1] *= sc0;
            O[nt][2] *= sc1; O[nt][3] *= sc1;
        }

        uint32_t Ph[4][4], Pl[4][4];
#pragma unroll
        for (int s = 0; s < 4; s++) {
            splitpack(Sa[2 * s][0],     Sa[2 * s][1],     Ph[s][0], Pl[s][0]);
            splitpack(Sa[2 * s][2],     Sa[2 * s][3],     Ph[s][1], Pl[s][1]);
            splitpack(Sa[2 * s + 1][0], Sa[2 * s + 1][1], Ph[s][2], Pl[s][2]);
            splitpack(Sa[2 * s + 1][2], Sa[2 * s + 1][3], Ph[s][3], Pl[s][3]);
        }

#pragma unroll
        for (int s = 0; s < 4; s++) {
            uint32_t B[8][2];
#pragma unroll
            for (int p = 0; p < 4; p++) {
                uint32_t r0, r1, r2, r3;
                LDSM_X4_T(r0, r1, r2, r3,
                          vhB + (s * 16 + vRow) * FSTR + (p * 16 + vCol) * 2);
                B[2 * p][0] = r0; B[2 * p][1] = r1;
                B[2 * p + 1][0] = r2; B[2 * p + 1][1] = r3;
            }
#pragma unroll
            for (int nt = 0; nt < 8; nt++) mma_bf16(O[nt], Ph[s], B[nt][0], B[nt][1]);
#pragma unroll
            for (int nt = 0; nt < 8; nt++) mma_bf16(O[nt], Pl[s], B[nt][0], B[nt][1]);
#pragma unroll
            for (int p = 0; p < 4; p++) {
                uint32_t r0, r1, r2, r3;
                LDSM_X4_T(r0, r1, r2, r3,
                          vlB + (s * 16 + vRow) * FSTR + (p * 16 + vCol) * 2);
                B[2 * p][0] = r0; B[2 * p][1] = r1;
                B[2 * p + 1][0] = r2; B[2 * p + 1][1] = r3;
            }
#pragma unroll
            for (int nt = 0; nt < 8; nt++) mma_bf16(O[nt], Ph[s], B[nt][0], B[nt][1]);
        }
        __syncthreads();
    }

    // ---- finalize: write rep hi/lo bf16 (feeds output projection) ----
    const float inv0 = 1.f / l0, inv1 = 1.f / l1;
    const int row0 = qt * 128 + wid * 16 + g;
    uint32_t* rh32 = reinterpret_cast<uint32_t*>(Rh) + (base >> 1);
    uint32_t* rl32 = reinterpret_cast<uint32_t*>(Rl) + (base >> 1);
    const uint32_t r0 = (uint32_t)row0 * (HD >> 1);
    const uint32_t r1 = (uint32_t)(row0 + 8) * (HD >> 1);
    const int qc = 2 * t4;
#pragma unroll
    for (int nt = 0; nt < 8; nt++) {
        const uint32_t cp = (uint32_t)(nt * 8 + qc) >> 1;
        uint32_t h0, lo0, h1, lo1;
        splitpack(O[nt][0] * inv0, O[nt][1] * inv0, h0, lo0);
        splitpack(O[nt][2] * inv1, O[nt][3] * inv1, h1, lo1);
        rh32[r0 + cp] = h0; rl32[r0 + cp] = lo0;
        rh32[r1 + cp] = h1; rl32[r1 + cp] = lo1;
    }
}

// =====================================================================
// launcher
// =====================================================================
extern "C" void kernel_launch(void* const* d_in, const int* in_sizes, int n_in,
                              void* d_out, int out_size)
{
    const float* x  = (const float*)d_in[0];
    const float* Wq = (const float*)d_in[1];
    const float* bq = (const float*)d_in[2];
    const float* Wk = (const float*)d_in[3];
    const float* bk = (const float*)d_in[4];
    const float* Wv = (const float*)d_in[5];
    const float* bv = (const float*)d_in[6];
    const float* Wo = (const float*)d_in[7];
    const float* bo = (const float*)d_in[8];

    __nv_bfloat16 *xh, *xl, *wht, *wlt, *qh, *ql, *kh, *kl, *vh, *vl, *rh, *rl;
    cudaGetSymbolAddress((void**)&xh,  g_xh);
    cudaGetSymbolAddress((void**)&xl,  g_xl);
    cudaGetSymbolAddress((void**)&wht, g_wht);
    cudaGetSymbolAddress((void**)&wlt, g_wlt);
    cudaGetSymbolAddress((void**)&qh,  g_Qh);
    cudaGetSymbolAddress((void**)&ql,  g_Ql);
    cudaGetSymbolAddress((void**)&kh,  g_Kh);
    cudaGetSymbolAddress((void**)&kl,  g_Kl);
    cudaGetSymbolAddress((void**)&vh,  g_Vh);
    cudaGetSymbolAddress((void**)&vl,  g_Vl);
    cudaGetSymbolAddress((void**)&rh,  g_Rh);
    cudaGetSymbolAddress((void**)&rl,  g_Rl);

    cudaFuncSetAttribute(flash_hmma,
                         cudaFuncAttributeMaxDynamicSharedMemorySize, FLASH_SMEM);
    cudaFuncSetAttribute(gemm_hmma3<0>,
                         cudaFuncAttributeMaxDynamicSharedMemorySize, GEMM_SMEM);
    cudaFuncSetAttribute(gemm_hmma3<1>,
                         cudaFuncAttributeMaxDynamicSharedMemorySize, GEMM_SMEM);

    const int n4 = Mrows * Dz / 4;
    const dim3 wgrid(Dz / 32, Dz / 32);
    const dim3 wblk(32, 8);

    // input split + concatenated W^T split
    split_kernel<<<2048, 256>>>((const float4*)x, (__nv_bfloat162*)xh, (__nv_bfloat162*)xl, n4);
    wsplit_kernel<<<wgrid, wblk>>>(Wq, wht,                       wlt);
    wsplit_kernel<<<wgrid, wblk>>>(Wk, wht + (size_t)Dz * Dz,     wlt + (size_t)Dz * Dz);
    wsplit_kernel<<<wgrid, wblk>>>(Wv, wht + (size_t)2 * Dz * Dz, wlt + (size_t)2 * Dz * Dz);

    // fused QKV projection: N=3072, epilogue splits to bf16 hi/lo
    gemm_hmma3<0><<<dim3(3 * Dz / 128, Mrows / 128), 256, GEMM_SMEM>>>(
        xh, xl, wht, wlt, bq, bk, bv, nullptr,
        qh, ql, kh, kl, vh, vl);

    flash_hmma<<<dim3(Pz / 128, Hz, Bz), 256, FLASH_SMEM>>>(
        qh, ql, kh, kl, vh, vl, rh, rl);

    // output projection
    wsplit_kernel<<<wgrid, wblk>>>(Wo, wht, wlt);
    gemm_hmma3<1><<<dim3(Dz / 128, Mrows / 128), 256, GEMM_SMEM>>>(
        rh, rl, wht, wlt, bo, nullptr, nullptr, (float*)d_out,
        nullptr, nullptr, nullptr, nullptr, nullptr, nullptr);
}

// round 12
// speedup vs baseline: 3.1649x; 1.0330x over previous
#include <cuda_runtime.h>
#include <cuda_bf16.h>
#include <cstdint>
#include <math.h>

// Problem constants
constexpr int Bz  = 4;
constexpr int Pz  = 2048;
constexpr int Dz  = 1024;
constexpr int Hz  = 16;
constexpr int DKz = 64;
constexpr int Mrows = Bz * Pz;          // 8192
constexpr int HD   = Hz * DKz;          // 1024

// ---------------- scratch (allocation-free rule: __device__ globals) -------
__device__ __nv_bfloat16 g_xh [(size_t)Mrows * Dz];
__device__ __nv_bfloat16 g_xl [(size_t)Mrows * Dz];
__device__ __nv_bfloat16 g_wht[(size_t)3 * Dz * Dz];   // QKV W^T hi [3072,1024]
__device__ __nv_bfloat16 g_wlt[(size_t)3 * Dz * Dz];
__device__ __nv_bfloat16 g_woh[(size_t)Dz * Dz];       // Wo^T hi
__device__ __nv_bfloat16 g_wol[(size_t)Dz * Dz];       // Wo^T lo
__device__ __nv_bfloat16 g_Qh [(size_t)Mrows * HD];
__device__ __nv_bfloat16 g_Ql [(size_t)Mrows * HD];
__device__ __nv_bfloat16 g_Kh [(size_t)Mrows * HD];
__device__ __nv_bfloat16 g_Kl [(size_t)Mrows * HD];
__device__ __nv_bfloat16 g_Vh [(size_t)Mrows * HD];
__device__ __nv_bfloat16 g_Vl [(size_t)Mrows * HD];
__device__ __nv_bfloat16 g_Rh [(size_t)Mrows * HD];
__device__ __nv_bfloat16 g_Rl [(size_t)Mrows * HD];

// =====================================================================
// baseline-PTX helpers (work on .target sm_103: no 'a' features!)
// =====================================================================
__device__ __forceinline__ uint32_t smem_u32(const void* p) {
    uint32_t a;
    asm("{ .reg .u64 t; cvta.to.shared.u64 t, %1; cvt.u32.u64 %0, t; }"
        : "=r"(a) : "l"(p));
    return a;
}
#define LDSM_X4(r0, r1, r2, r3, addr) \
    asm volatile("ldmatrix.sync.aligned.m8n8.x4.shared.b16 {%0,%1,%2,%3}, [%4];" \
                 : "=r"(r0), "=r"(r1), "=r"(r2), "=r"(r3) : "r"(addr))
#define LDSM_X4_T(r0, r1, r2, r3, addr) \
    asm volatile("ldmatrix.sync.aligned.m8n8.x4.trans.shared.b16 {%0,%1,%2,%3}, [%4];" \
                 : "=r"(r0), "=r"(r1), "=r"(r2), "=r"(r3) : "r"(addr))
#define CP_ASYNC16(dst, src) \
    asm volatile("cp.async.ca.shared.global [%0], [%1], 16;" :: "r"(dst), "l"(src))
#define CP_COMMIT() asm volatile("cp.async.commit_group;" ::: "memory")
#define CP_WAIT1()  asm volatile("cp.async.wait_group 1;" ::: "memory")
#define CP_WAIT0()  asm volatile("cp.async.wait_group 0;" ::: "memory")

__device__ __forceinline__ void mma_bf16(float* c, const uint32_t a[4],
                                         uint32_t b0, uint32_t b1) {
    asm volatile(
        "mma.sync.aligned.m16n8k16.row.col.f32.bf16.bf16.f32 "
        "{%0,%1,%2,%3}, {%4,%5,%6,%7}, {%8,%9}, {%0,%1,%2,%3};"
        : "+f"(c[0]), "+f"(c[1]), "+f"(c[2]), "+f"(c[3])
        : "r"(a[0]), "r"(a[1]), "r"(a[2]), "r"(a[3]), "r"(b0), "r"(b1));
}

// fast exp on FMA pipe (avoids the chip-wide MUFU floor)
__device__ __forceinline__ float fast_exp(float x) {
    float t = fmaxf(x * 1.4426950408889634f, -126.0f);
    float r = t + 12582912.0f;
    float i = r - 12582912.0f;
    float f = t - i;
    float p = 1.3333558e-3f;
    p = fmaf(p, f, 9.6181291e-3f);
    p = fmaf(p, f, 5.5504109e-2f);
    p = fmaf(p, f, 2.4022651e-1f);
    p = fmaf(p, f, 6.9314718e-1f);
    p = fmaf(p, f, 1.0f);
    float s = __int_as_float(((int)i + 127) << 23);
    return p * s;
}

__device__ __forceinline__ void split2(float x, __nv_bfloat16& h, __nv_bfloat16& l) {
    h = __float2bfloat16_rn(x);
    l = __float2bfloat16_rn(x - __bfloat162float(h));
}
__device__ __forceinline__ uint32_t pk2(__nv_bfloat16 a, __nv_bfloat16 b) {
    __nv_bfloat162 v; v.x = a; v.y = b;
    return reinterpret_cast<uint32_t&>(v);
}
__device__ __forceinline__ void splitpack(float a, float b, uint32_t& hi, uint32_t& lo) {
    __nv_bfloat16 ah, al, bh, bl;
    split2(a, ah, al); split2(b, bh, bl);
    hi = pk2(ah, bh); lo = pk2(al, bl);
}

// =====================================================================
// input split kernels
// =====================================================================
__global__ void split_kernel(const float4* __restrict__ src,
                             __nv_bfloat162* __restrict__ hi,
                             __nv_bfloat162* __restrict__ lo, int n4)
{
    int i = blockIdx.x * blockDim.x + threadIdx.x;
    int stride = gridDim.x * blockDim.x;
    for (; i < n4; i += stride) {
        float4 v = src[i];
        __nv_bfloat16 h0, h1, h2, h3, l0, l1, l2, l3;
        split2(v.x, h0, l0); split2(v.y, h1, l1);
        split2(v.z, h2, l2); split2(v.w, h3, l3);
        hi[2 * i]     = __halves2bfloat162(h0, h1);
        hi[2 * i + 1] = __halves2bfloat162(h2, h3);
        lo[2 * i]     = __halves2bfloat162(l0, l1);
        lo[2 * i + 1] = __halves2bfloat162(l2, l3);
    }
}

__global__ void wsplit_kernel(const float* __restrict__ W,
                              __nv_bfloat16* __restrict__ WhT,
                              __nv_bfloat16* __restrict__ WlT)
{
    __shared__ float s[32][33];
    const int n0 = blockIdx.x * 32, k0 = blockIdx.y * 32;
    const int tx = threadIdx.x, ty = threadIdx.y;   // (32, 8)
#pragma unroll
    for (int i = 0; i < 4; i++)
        s[ty + i * 8][tx] = W[(size_t)(k0 + ty + i * 8) * Dz + n0 + tx];
    __syncthreads();
#pragma unroll
    for (int i = 0; i < 4; i++) {
        const int n = n0 + ty + i * 8;
        const int k = k0 + tx;
        __nv_bfloat16 h, l;
        split2(s[tx][ty + i * 8], h, l);
        WhT[(size_t)n * Dz + k] = h;
        WlT[(size_t)n * Dz + k] = l;
    }
}

// =====================================================================
// HMMA split-bf16 GEMM, CTA 128x128, 8 warps of 64x32, BK=32, occ 2.
// EPI=0: QKV fused epilogue -> bf16 hi/lo per 1024-col segment (Q x 1/8)
// EPI=1: fp32 out + bias (output projection)
// =====================================================================
constexpr int SKB   = 80;
constexpr int TILEB = 128 * SKB;           // 10240
constexpr int BUFB  = 4 * TILEB;           // 40960
constexpr int GEMM_SMEM = 2 * BUFB;        // 81920

template<int EPI>
__global__ __launch_bounds__(256, 2)
void gemm_hmma3(const __nv_bfloat16* __restrict__ Ah, const __nv_bfloat16* __restrict__ Al,
                const __nv_bfloat16* __restrict__ Bh, const __nv_bfloat16* __restrict__ Bl,
                const float* __restrict__ b0p, const float* __restrict__ b1p,
                const float* __restrict__ b2p,
                float* __restrict__ Cf,
                __nv_bfloat16* __restrict__ QH, __nv_bfloat16* __restrict__ QL,
                __nv_bfloat16* __restrict__ KH, __nv_bfloat16* __restrict__ KL,
                __nv_bfloat16* __restrict__ VH, __nv_bfloat16* __restrict__ VL)
{
    extern __shared__ char smem[];
    const uint32_t sbase = smem_u32(smem);
    const int tid  = threadIdx.x;
    const int lane = tid & 31;
    const int wid  = tid >> 5;
    const int wm   = wid >> 2;       // 0..1  (64 rows each)
    const int wn   = wid & 3;        // 0..3  (32 cols each)
    const int m0 = blockIdx.y * 128;
    const int n0 = blockIdx.x * 128;

    const __nv_bfloat16* srcs[4] = {
        Ah + (size_t)m0 * Dz, Al + (size_t)m0 * Dz,
        Bh + (size_t)n0 * Dz, Bl + (size_t)n0 * Dz };

    float acc[4][4][4];
#pragma unroll
    for (int mi = 0; mi < 4; mi++)
#pragma unroll
        for (int ni = 0; ni < 4; ni++)
#pragma unroll
            for (int r = 0; r < 4; r++) acc[mi][ni][r] = 0.f;

    auto issue = [&](int t, int b) {
#pragma unroll
        for (int p = 0; p < 4; p++) {
            const __nv_bfloat16* s = srcs[p] + t * 32;
            const uint32_t dT = sbase + b * BUFB + p * TILEB;
#pragma unroll
            for (int i = 0; i < 2; i++) {
                int lin = tid + i * 256;           // 0..511
                int row = lin >> 2, kg = lin & 3;
                CP_ASYNC16(dT + row * SKB + kg * 16, s + (size_t)row * Dz + kg * 8);
            }
        }
        CP_COMMIT();
    };

    const uint32_t aRow = lane & 15;
    const uint32_t aK   = (lane >> 4) * 8;
    const uint32_t bN   = ((lane >> 4) & 1) * 8 + (lane & 7);
    const uint32_t bK   = ((lane >> 3) & 1) * 8;

    issue(0, 0);
    const int nk = Dz / 32;                        // 32
    for (int t = 0; t < nk; t++) {
        if (t + 1 < nk) { issue(t + 1, (t + 1) & 1); CP_WAIT1(); }
        else            { CP_WAIT0(); }
        __syncthreads();

        const uint32_t bb  = sbase + (t & 1) * BUFB;
        const uint32_t ahB = bb, alB = bb + TILEB;
        const uint32_t bhB = bb + 2 * TILEB, blB = bb + 3 * TILEB;

#pragma unroll
        for (int ks = 0; ks < 32; ks += 16) {
            const uint32_t aoff = (aK + ks) * 2;
            const uint32_t boff = (bK + ks) * 2;

            uint32_t Ahf[4][4], Bhf[4][2];
#pragma unroll
            for (int p = 0; p < 2; p++) {
                uint32_t r0, r1, r2, r3;
                LDSM_X4(r0, r1, r2, r3, bhB + (wn * 32 + p * 16 + bN) * SKB + boff);
                Bhf[2 * p][0] = r0; Bhf[2 * p][1] = r1;
                Bhf[2 * p + 1][0] = r2; Bhf[2 * p + 1][1] = r3;
            }
#pragma unroll
            for (int mi = 0; mi < 4; mi++)
                LDSM_X4(Ahf[mi][0], Ahf[mi][1], Ahf[mi][2], Ahf[mi][3],
                        ahB + (wm * 64 + mi * 16 + aRow) * SKB + aoff);
            // term 1: Ah x Bh
#pragma unroll
            for (int mi = 0; mi < 4; mi++)
#pragma unroll
                for (int ni = 0; ni < 4; ni++)
                    mma_bf16(acc[mi][ni], Ahf[mi], Bhf[ni][0], Bhf[ni][1]);
            // term 2: Al x Bh
#pragma unroll
            for (int mi = 0; mi < 4; mi++) {
                uint32_t Alf[4];
                LDSM_X4(Alf[0], Alf[1], Alf[2], Alf[3],
                        alB + (wm * 64 + mi * 16 + aRow) * SKB + aoff);
#pragma unroll
                for (int ni = 0; ni < 4; ni++)
                    mma_bf16(acc[mi][ni], Alf, Bhf[ni][0], Bhf[ni][1]);
            }
            // term 3: Ah x Bl
#pragma unroll
            for (int p = 0; p < 2; p++) {
                uint32_t r0, r1, r2, r3;
                LDSM_X4(r0, r1, r2, r3, blB + (wn * 32 + p * 16 + bN) * SKB + boff);
#pragma unroll
                for (int mi = 0; mi < 4; mi++) {
                    mma_bf16(acc[mi][2 * p],     Ahf[mi], r0, r1);
                    mma_bf16(acc[mi][2 * p + 1], Ahf[mi], r2, r3);
                }
            }
        }
        __syncthreads();
    }

    const int g  = lane >> 2;
    const int c2 = (lane & 3) * 2;

    if (EPI == 1) {
        // fp32 + bias (output projection); N=1024
#pragma unroll
        for (int mi = 0; mi < 4; mi++) {
            const int row = m0 + wm * 64 + mi * 16 + g;
#pragma unroll
            for (int ni = 0; ni < 4; ni++) {
                const int col = n0 + wn * 32 + ni * 8 + c2;
                const float2 bb = *reinterpret_cast<const float2*>(b0p + col);
                float2 v0 = { acc[mi][ni][0] + bb.x, acc[mi][ni][1] + bb.y };
                float2 v1 = { acc[mi][ni][2] + bb.x, acc[mi][ni][3] + bb.y };
                *reinterpret_cast<float2*>(Cf + (size_t)row * Dz + col)       = v0;
                *reinterpret_cast<float2*>(Cf + (size_t)(row + 8) * Dz + col) = v1;
            }
        }
    } else {
        // QKV routed epilogue: CTA N-tile (128) lies inside one 1024-col segment
        const int seg = n0 >> 10;                  // 0,1,2
        const float* bias = (seg == 0) ? b0p : (seg == 1) ? b1p : b2p;
        const float scale = (seg == 0) ? 0.125f : 1.0f;
        uint32_t* oh = reinterpret_cast<uint32_t*>(seg == 0 ? QH : seg == 1 ? KH : VH);
        uint32_t* ol = reinterpret_cast<uint32_t*>(seg == 0 ? QL : seg == 1 ? KL : VL);
        const int nsegBase = n0 & 1023;
#pragma unroll
        for (int mi = 0; mi < 4; mi++) {
            const int row0 = m0 + wm * 64 + mi * 16 + g;
#pragma unroll
            for (int ni = 0; ni < 4; ni++) {
                const int col = nsegBase + wn * 32 + ni * 8 + c2;   // even
                const float2 bb = *reinterpret_cast<const float2*>(bias + col);
                float v00 = (acc[mi][ni][0] + bb.x) * scale;
                float v01 = (acc[mi][ni][1] + bb.y) * scale;
                float v10 = (acc[mi][ni][2] + bb.x) * scale;
                float v11 = (acc[mi][ni][3] + bb.y) * scale;
                uint32_t h0, l0v, h1, l1v;
                splitpack(v00, v01, h0, l0v);
                splitpack(v10, v11, h1, l1v);
                const uint32_t i0 = ((uint32_t)row0 * Dz + col) >> 1;
                const uint32_t i1 = i0 + (8 * Dz >> 1);
                oh[i0] = h0; ol[i0] = l0v;
                oh[i1] = h1; ol[i1] = l1v;
            }
        }
    }
}

// =====================================================================
// HMMA flash attention. Q now staged in SMEM (ldmatrix A-path, same as
// GEMM's proven A operand) -> ~120 live regs -> __launch_bounds__(256,2)
// gives 2 CTAs/SM (smem 110592 x 2 = 216KB <= 227KB cap).
// =====================================================================
constexpr int FSTR  = 144;
constexpr int QTILE = 128 * FSTR;                  // 18432 (one of hi/lo)
constexpr int FTILE = 64 * FSTR;                   // 9216
constexpr int FBUF  = 4 * FTILE;                   // 36864
constexpr int FLASH_SMEM = 2 * QTILE + 2 * FBUF;   // 110592

__global__ __launch_bounds__(256, 2)
void flash_hmma(const __nv_bfloat16* __restrict__ Qhp, const __nv_bfloat16* __restrict__ Qlp,
                const __nv_bfloat16* __restrict__ Kh, const __nv_bfloat16* __restrict__ Kl,
                const __nv_bfloat16* __restrict__ Vh, const __nv_bfloat16* __restrict__ Vl,
                __nv_bfloat16* __restrict__ Rh, __nv_bfloat16* __restrict__ Rl)
{
    extern __shared__ char smem[];
    const uint32_t sbase = smem_u32(smem);
    const int tid = threadIdx.x, lane = tid & 31, wid = tid >> 5;
    const int g = lane >> 2, t4 = lane & 3;
    const int qt = blockIdx.x, h = blockIdx.y, b = blockIdx.z;
    const size_t base = (size_t)b * Pz * HD + (size_t)h * DKz;

    const uint32_t qhB = sbase;
    const uint32_t qlB = sbase + QTILE;
    const uint32_t kvB = sbase + 2 * QTILE;

    // ---- Q tile (128 rows x 64 dk, hi+lo) -> SMEM via cp.async ----
    {
        const __nv_bfloat16* qsrc[2] = {
            Qhp + base + (size_t)(qt * 128) * HD,
            Qlp + base + (size_t)(qt * 128) * HD };
#pragma unroll
        for (int p = 0; p < 2; p++) {
            const uint32_t dT = (p == 0) ? qhB : qlB;
#pragma unroll
            for (int i = 0; i < 4; i++) {
                int lin = tid + i * 256;           // 0..1023
                int row = lin >> 3, ch = lin & 7;
                CP_ASYNC16(dT + row * FSTR + ch * 16,
                           qsrc[p] + (size_t)row * HD + ch * 8);
            }
        }
        CP_COMMIT();
    }

    const __nv_bfloat16* srcs[4] = { Kh + base, Kl + base, Vh + base, Vl + base };

    auto issue = [&](int tt, int bf) {
#pragma unroll
        for (int p = 0; p < 4; p++) {
            const __nv_bfloat16* s = srcs[p] + (size_t)(tt * 64) * HD;
            const uint32_t dT = kvB + bf * FBUF + p * FTILE;
#pragma unroll
            for (int i = 0; i < 2; i++) {
                int lin = tid + i * 256;
                int row = lin >> 3, ch = lin & 7;
                CP_ASYNC16(dT + row * FSTR + ch * 16, s + (size_t)row * HD + ch * 8);
            }
        }
        CP_COMMIT();
    };

    // ldmatrix lane address components
    const uint32_t aRow = lane & 15;                           // Q A-frag rows
    const uint32_t aK   = (lane >> 4) * 8;                     // Q A-frag k half
    const uint32_t bN = ((lane >> 4) & 1) * 8 + (lane & 7);    // K non-trans
    const uint32_t bK = ((lane >> 3) & 1) * 8;
    const uint32_t part = lane >> 3;                           // V trans
    const uint32_t vRow = (part & 1) * 8 + (lane & 7);
    const uint32_t vCol = (part >> 1) * 8;
    const uint32_t qrowOff = (wid * 16 + aRow) * FSTR;

    float O[8][4];
#pragma unroll
    for (int nt = 0; nt < 8; nt++)
#pragma unroll
        for (int r = 0; r < 4; r++) O[nt][r] = 0.f;
    float m0 = -1e30f, m1 = -1e30f, l0 = 0.f, l1 = 0.f;

    issue(0, 0);
    const int nT = Pz / 64;
    for (int t = 0; t < nT; t++) {
        if (t + 1 < nT) { issue(t + 1, (t + 1) & 1); CP_WAIT1(); }
        else            { CP_WAIT0(); }
        __syncthreads();

        const uint32_t bb = kvB + (t & 1) * FBUF;
        const uint32_t khB = bb, klB = bb + FTILE;
        const uint32_t vhB = bb + 2 * FTILE, vlB = bb + 3 * FTILE;

        // ---- S = (Qh+Ql)(Kh+Kl)^T, 3 terms; Q frags from SMEM ----
        float Sa[8][4];
#pragma unroll
        for (int nt = 0; nt < 8; nt++)
#pragma unroll
            for (int r = 0; r < 4; r++) Sa[nt][r] = 0.f;

#pragma unroll
        for (int s = 0; s < 4; s++) {
            const uint32_t qoff = (aK + s * 16) * 2;
            uint32_t Qhf[4], Qlf[4];
            LDSM_X4(Qhf[0], Qhf[1], Qhf[2], Qhf[3], qhB + qrowOff + qoff);
            LDSM_X4(Qlf[0], Qlf[1], Qlf[2], Qlf[3], qlB + qrowOff + qoff);

            uint32_t B[8][2];
#pragma unroll
            for (int p = 0; p < 4; p++) {
                uint32_t r0, r1, r2, r3;
                LDSM_X4(r0, r1, r2, r3, khB + (p * 16 + bN) * FSTR + (bK + s * 16) * 2);
                B[2 * p][0] = r0; B[2 * p][1] = r1;
                B[2 * p + 1][0] = r2; B[2 * p + 1][1] = r3;
            }
#pragma unroll
            for (int nt = 0; nt < 8; nt++) mma_bf16(Sa[nt], Qhf, B[nt][0], B[nt][1]);
#pragma unroll
            for (int nt = 0; nt < 8; nt++) mma_bf16(Sa[nt], Qlf, B[nt][0], B[nt][1]);
#pragma unroll
            for (int p = 0; p < 4; p++) {
                uint32_t r0, r1, r2, r3;
                LDSM_X4(r0, r1, r2, r3, klB + (p * 16 + bN) * FSTR + (bK + s * 16) * 2);
                B[2 * p][0] = r0; B[2 * p][1] = r1;
                B[2 * p + 1][0] = r2; B[2 * p + 1][1] = r3;
            }
#pragma unroll
            for (int nt = 0; nt < 8; nt++) mma_bf16(Sa[nt], Qhf, B[nt][0], B[nt][1]);
        }

        // ---- online softmax on fragments (rows g and g+8) ----
        float ml0 = -1e30f, ml1 = -1e30f;
#pragma unroll
        for (int nt = 0; nt < 8; nt++) {
            ml0 = fmaxf(ml0, fmaxf(Sa[nt][0], Sa[nt][1]));
            ml1 = fmaxf(ml1, fmaxf(Sa[nt][2], Sa[nt][3]));
        }
        ml0 = fmaxf(ml0, __shfl_xor_sync(0xffffffffu, ml0, 1));
        ml0 = fmaxf(ml0, __shfl_xor_sync(0xffffffffu, ml0, 2));
        ml1 = fmaxf(ml1, __shfl_xor_sync(0xffffffffu, ml1, 1));
        ml1 = fmaxf(ml1, __shfl_xor_sync(0xffffffffu, ml1, 2));
        const float mn0 = fmaxf(m0, ml0), mn1 = fmaxf(m1, ml1);
        const float sc0 = fast_exp(m0 - mn0), sc1 = fast_exp(m1 - mn1);
        m0 = mn0; m1 = mn1;

        float ps0 = 0.f, ps1 = 0.f;
#pragma unroll
        for (int nt = 0; nt < 8; nt++) {
            Sa[nt][0] = fast_exp(Sa[nt][0] - mn0);
            Sa[nt][1] = fast_exp(Sa[nt][1] - mn0);
            Sa[nt][2] = fast_exp(Sa[nt][2] - mn1);
            Sa[nt][3] = fast_exp(Sa[nt][3] - mn1);
            ps0 += Sa[nt][0] + Sa[nt][1];
            ps1 += Sa[nt][2] + Sa[nt][3];
        }
        ps0 += __shfl_xor_sync(0xffffffffu, ps0, 1);
        ps0 += __shfl_xor_sync(0xffffffffu, ps0, 2);
        ps1 += __shfl_xor_sync(0xffffffffu, ps1, 1);
        ps1 += __shfl_xor_sync(0xffffffffu, ps1, 2);
        l0 = l0 * sc0 + ps0;
        l1 = l1 * sc1 + ps1;

#pragma unroll
        for (int nt = 0; nt < 8; nt++) {
            O[nt][0] *= sc0; O[nt][1] *= sc0;
            O[nt][2] *= sc1; O[nt][3] *= sc1;
        }

        // ---- P fragments: S C-frag -> A-frag, split hi/lo ----
        uint32_t Ph[4][4], Pl[4][4];
#pragma unroll
        for (int s = 0; s < 4; s++) {
            splitpack(Sa[2 * s][0],     Sa[2 * s][1],     Ph[s][0], Pl[s][0]);
            splitpack(Sa[2 * s][2],     Sa[2 * s][3],     Ph[s][1], Pl[s][1]);
            splitpack(Sa[2 * s + 1][0], Sa[2 * s + 1][1], Ph[s][2], Pl[s][2]);
            splitpack(Sa[2 * s + 1][2], Sa[2 * s + 1][3], Ph[s][3], Pl[s][3]);
        }

        // ---- O += (Ph+Pl)(Vh+Vl), 3 terms ----
#pragma unroll
        for (int s = 0; s < 4; s++) {
            uint32_t B[8][2];
#pragma unroll
            for (int p = 0; p < 4; p++) {
                uint32_t r0, r1, r2, r3;
                LDSM_X4_T(r0, r1, r2, r3,
                          vhB + (s * 16 + vRow) * FSTR + (p * 16 + vCol) * 2);
                B[2 * p][0] = r0; B[2 * p][1] = r1;
                B[2 * p + 1][0] = r2; B[2 * p + 1][1] = r3;
            }
#pragma unroll
            for (int nt = 0; nt < 8; nt++) mma_bf16(O[nt], Ph[s], B[nt][0], B[nt][1]);
#pragma unroll
            for (int nt = 0; nt < 8; nt++) mma_bf16(O[nt], Pl[s], B[nt][0], B[nt][1]);
#pragma unroll
            for (int p = 0; p < 4; p++) {
                uint32_t r0, r1, r2, r3;
                LDSM_X4_T(r0, r1, r2, r3,
                          vlB + (s * 16 + vRow) * FSTR + (p * 16 + vCol) * 2);
                B[2 * p][0] = r0; B[2 * p][1] = r1;
                B[2 * p + 1][0] = r2; B[2 * p + 1][1] = r3;
            }
#pragma unroll
            for (int nt = 0; nt < 8; nt++) mma_bf16(O[nt], Ph[s], B[nt][0], B[nt][1]);
        }
        __syncthreads();
    }

    // ---- finalize: write rep hi/lo bf16 (feeds output projection) ----
    const float inv0 = 1.f / l0, inv1 = 1.f / l1;
    const int row0 = qt * 128 + wid * 16 + g;
    uint32_t* rh32 = reinterpret_cast<uint32_t*>(Rh) + (base >> 1);
    uint32_t* rl32 = reinterpret_cast<uint32_t*>(Rl) + (base >> 1);
    const uint32_t r0 = (uint32_t)row0 * (HD >> 1);
    const uint32_t r1 = (uint32_t)(row0 + 8) * (HD >> 1);
    const int qc = 2 * t4;
#pragma unroll
    for (int nt = 0; nt < 8; nt++) {
        const uint32_t cp = (uint32_t)(nt * 8 + qc) >> 1;
        uint32_t h0, lo0, h1, lo1;
        splitpack(O[nt][0] * inv0, O[nt][1] * inv0, h0, lo0);
        splitpack(O[nt][2] * inv1, O[nt][3] * inv1, h1, lo1);
        rh32[r0 + cp] = h0; rl32[r0 + cp] = lo0;
        rh32[r1 + cp] = h1; rl32[r1 + cp] = lo1;
    }
}

// =====================================================================
// launcher
// =====================================================================
extern "C" void kernel_launch(void* const* d_in, const int* in_sizes, int n_in,
                              void* d_out, int out_size)
{
    const float* x  = (const float*)d_in[0];
    const float* Wq = (const float*)d_in[1];
    const float* bq = (const float*)d_in[2];
    const float* Wk = (const float*)d_in[3];
    const float* bk = (const float*)d_in[4];
    const float* Wv = (const float*)d_in[5];
    const float* bv = (const float*)d_in[6];
    const float* Wo = (const float*)d_in[7];
    const float* bo = (const float*)d_in[8];

    __nv_bfloat16 *xh, *xl, *wht, *wlt, *woh, *wol;
    __nv_bfloat16 *qh, *ql, *kh, *kl, *vh, *vl, *rh, *rl;
    cudaGetSymbolAddress((void**)&xh,  g_xh);
    cudaGetSymbolAddress((void**)&xl,  g_xl);
    cudaGetSymbolAddress((void**)&wht, g_wht);
    cudaGetSymbolAddress((void**)&wlt, g_wlt);
    cudaGetSymbolAddress((void**)&woh, g_woh);
    cudaGetSymbolAddress((void**)&wol, g_wol);
    cudaGetSymbolAddress((void**)&qh,  g_Qh);
    cudaGetSymbolAddress((void**)&ql,  g_Ql);
    cudaGetSymbolAddress((void**)&kh,  g_Kh);
    cudaGetSymbolAddress((void**)&kl,  g_Kl);
    cudaGetSymbolAddress((void**)&vh,  g_Vh);
    cudaGetSymbolAddress((void**)&vl,  g_Vl);
    cudaGetSymbolAddress((void**)&rh,  g_Rh);
    cudaGetSymbolAddress((void**)&rl,  g_Rl);

    cudaFuncSetAttribute(flash_hmma,
                         cudaFuncAttributeMaxDynamicSharedMemorySize, FLASH_SMEM);
    cudaFuncSetAttribute(gemm_hmma3<0>,
                         cudaFuncAttributeMaxDynamicSharedMemorySize, GEMM_SMEM);
    cudaFuncSetAttribute(gemm_hmma3<1>,
                         cudaFuncAttributeMaxDynamicSharedMemorySize, GEMM_SMEM);

    const int n4 = Mrows * Dz / 4;
    const dim3 wgrid(Dz / 32, Dz / 32);
    const dim3 wblk(32, 8);

    // all splits upfront (Wo into its own buffer) — launch #6 = gemm<0>
    split_kernel<<<2048, 256>>>((const float4*)x, (__nv_bfloat162*)xh, (__nv_bfloat162*)xl, n4);
    wsplit_kernel<<<wgrid, wblk>>>(Wq, wht,                       wlt);
    wsplit_kernel<<<wgrid, wblk>>>(Wk, wht + (size_t)Dz * Dz,     wlt + (size_t)Dz * Dz);
    wsplit_kernel<<<wgrid, wblk>>>(Wv, wht + (size_t)2 * Dz * Dz, wlt + (size_t)2 * Dz * Dz);
    wsplit_kernel<<<wgrid, wblk>>>(Wo, woh, wol);

    // fused QKV projection: N=3072, epilogue splits to bf16 hi/lo
    gemm_hmma3<0><<<dim3(3 * Dz / 128, Mrows / 128), 256, GEMM_SMEM>>>(
        xh, xl, wht, wlt, bq, bk, bv, nullptr,
        qh, ql, kh, kl, vh, vl);

    flash_hmma<<<dim3(Pz / 128, Hz, Bz), 256, FLASH_SMEM>>>(
        qh, ql, kh, kl, vh, vl, rh, rl);

    // output projection
    gemm_hmma3<1><<<dim3(Dz / 128, Mrows / 128), 256, GEMM_SMEM>>>(
        rh, rl, woh, wol, bo, nullptr, nullptr, (float*)d_out,
        nullptr, nullptr, nullptr, nullptr, nullptr, nullptr);
}